// round 12
// baseline (speedup 1.0000x reference)
#include <cuda_runtime.h>
#include <cuda_fp16.h>
#include <math.h>
#include <stdint.h>

// ---------------- problem constants ----------------
#define Bq   64
#define Dd   768
#define Nn   262144
#define Vv   50257
#define Kk   8
#define TEMP 10.0f
#define LAM  0.25f
#define EPSV 1e-10f

#define KPC    256                 // keys per CTA
#define NCHUNK (Nn / KPC)          // 1024
#define NKC    24                  // 768/32 d-tiles
#define TOPC   16                  // candidates rescored exactly

// smem layout (bytes)
#define K32P   144                 // fp32 K row pitch (36 floats; conflict-free)
#define K32STG (KPC * K32P)        // 36864 per fp32 stage (3 stages @ 0)
#define KHP    80                  // fp16 K row pitch (ldmatrix, conflict-free)
#define KHSTG  (KPC * KHP)         // 20480 per fp16 stage (2 stages)
#define SMO_KH   (3 * K32STG)      // 110592
#define QPITCH 80
#define QSTG   (64 * QPITCH)       // 5120 per Q slot (4 slots)
#define SMO_QBUF (SMO_KH + 2 * KHSTG)          // 151552
#define SMO_K2   (SMO_QBUF + 4 * QSTG)         // 172032
#define SMEM_BYTES (SMO_K2 + 1024)             // 173056

// ---------------- scratch ----------------
__device__ float  g_cs[Bq * NCHUNK * Kk];
__device__ int    g_ci[Bq * NCHUNK * Kk];
__device__ float  g_w[Bq * Kk];
__device__ int    g_tok[Bq * Kk];
__device__ float  g_sumw[Bq];
__device__ float  g_pm[Bq * 4];
__device__ float  g_ps[Bq * 4];
__device__ __half g_qh[Bq * Dd];           // fp16 Q

// ---------------- helpers ----------------
__device__ __forceinline__ unsigned smem_u32(const void* p) {
    unsigned a;
    asm("{ .reg .u64 t; cvta.to.shared.u64 t, %1; cvt.u32.u64 %0, t; }" : "=r"(a) : "l"(p));
    return a;
}
__device__ __forceinline__ void cp16(unsigned dst, const void* src) {
    asm volatile("cp.async.cg.shared.global [%0], [%1], 16;" :: "r"(dst), "l"(src));
}
__device__ __forceinline__ void cp_commit() { asm volatile("cp.async.commit_group;" ::: "memory"); }
template<int N> __device__ __forceinline__ void cp_wait() { asm volatile("cp.async.wait_group %0;" :: "n"(N) : "memory"); }

__device__ __forceinline__ unsigned cvt_h2(float lo, float hi) {
    unsigned r;
    asm("cvt.rn.f16x2.f32 %0, %1, %2;" : "=r"(r) : "f"(hi), "f"(lo));
    return r;
}
__device__ __forceinline__ void ldm4(unsigned r[4], unsigned addr) {
    asm volatile("ldmatrix.sync.aligned.m8n8.x4.shared.b16 {%0,%1,%2,%3}, [%4];"
                 : "=r"(r[0]), "=r"(r[1]), "=r"(r[2]), "=r"(r[3]) : "r"(addr));
}
__device__ __forceinline__ void sts64(unsigned addr, unsigned w0, unsigned w1) {
    asm volatile("st.shared.v2.b32 [%0], {%1,%2};" :: "r"(addr), "r"(w0), "r"(w1));
}
__device__ __forceinline__ void mma_f16(float c[4],
                                        unsigned a0, unsigned a1, unsigned a2, unsigned a3,
                                        unsigned b0, unsigned b1) {
    asm volatile(
        "mma.sync.aligned.m16n8k16.row.col.f32.f16.f16.f32 "
        "{%0,%1,%2,%3}, {%4,%5,%6,%7}, {%8,%9}, {%0,%1,%2,%3};"
        : "+f"(c[0]), "+f"(c[1]), "+f"(c[2]), "+f"(c[3])
        : "r"(a0), "r"(a1), "r"(a2), "r"(a3), "r"(b0), "r"(b1));
}

// =====================================================================
// Dummy kernel (aligns ncu capture slot onto k_scores = 4th launch)
// =====================================================================
__global__ void k_dummy() {}

// =====================================================================
// Kernel 0: Q fp32 -> fp16 global
// =====================================================================
__global__ __launch_bounds__(512)
void k_prepq(const float* __restrict__ qh) {
    int i = blockIdx.x * 512 + threadIdx.x;
    if (i < Bq * Dd) g_qh[i] = __float2half_rn(qh[i]);
}

// =====================================================================
// Kernel 1: fp16 MMA, single barrier per kc.
// 3-stage fp32 K (cp.async), 2-stage fp16 KH, 4-slot Q.
// Iteration kc: sync; MMA(kc-1) || pack(kc) || cp-issue(kc+2).
// =====================================================================
__device__ __forceinline__ void issue_stage(unsigned smb, int tid,
                                            const float* __restrict__ keys,
                                            int kBase, int kc) {
    const int r0 = tid >> 3, jw = tid & 7;
    const unsigned kdst0 = smb + (kc % 3) * K32STG + jw * 16;
    const float* ksrc0 = keys + (size_t)(kBase + r0) * Dd + kc * 32 + jw * 4;
    #pragma unroll
    for (int p = 0; p < 8; ++p)
        cp16(kdst0 + (r0 + 32 * p) * K32P, ksrc0 + (size_t)(32 * p) * Dd);
    const int qr = tid >> 2, qc = tid & 3;
    cp16(smb + SMO_QBUF + (kc & 3) * QSTG + qr * QPITCH + qc * 16,
         g_qh + qr * Dd + kc * 32 + qc * 8);
}

__device__ __forceinline__ void do_mma(float c[2][8][4], unsigned kst, unsigned qst) {
    #pragma unroll
    for (int ks = 0; ks < 2; ++ks) {
        unsigned A0[4], A1[4];
        ldm4(A0, kst + ks * 32);
        ldm4(A1, kst + 16 * KHP + ks * 32);
        #pragma unroll
        for (int np = 0; np < 4; ++np) {
            unsigned B[4];
            ldm4(B, qst + np * (16 * QPITCH) + ks * 32);
            mma_f16(c[0][2 * np],     A0[0], A0[1], A0[2], A0[3], B[0], B[1]);
            mma_f16(c[0][2 * np + 1], A0[0], A0[1], A0[2], A0[3], B[2], B[3]);
            mma_f16(c[1][2 * np],     A1[0], A1[1], A1[2], A1[3], B[0], B[1]);
            mma_f16(c[1][2 * np + 1], A1[0], A1[1], A1[2], A1[3], B[2], B[3]);
        }
    }
}

__global__ void __launch_bounds__(256, 1)
k_scores_f16(const float* __restrict__ keys) {
    extern __shared__ char sm[];
    const unsigned smb = smem_u32(sm);
    float* k2s = (float*)(sm + SMO_K2);
    float* sT  = (float*)sm;                     // 64 x 264 f32, post-mainloop

    const int tid = threadIdx.x;
    const int w = tid >> 5, lane = tid & 31;
    const int g = lane >> 2, t = lane & 3;
    const int kBase = blockIdx.x * KPC;

    // ldmatrix lane address bases (rd8-proven mapping)
    const unsigned aRow = (lane & 7) + ((lane >> 3) & 1) * 8;
    const unsigned aCol = (lane >> 4) * 16;
    const unsigned aBase = smb + SMO_KH + (w * 32 + aRow) * KHP + aCol;
    const unsigned bRow = lane & 7;
    const unsigned bNt  = (lane >> 4) & 1;
    const unsigned bKo  = ((lane >> 3) & 1) * 16;
    const unsigned bBase = smb + SMO_QBUF + (bNt * 8 + bRow) * QPITCH + bKo;

    float c[2][8][4];
    #pragma unroll
    for (int m = 0; m < 2; ++m)
        #pragma unroll
        for (int n = 0; n < 8; ++n)
            #pragma unroll
            for (int v = 0; v < 4; ++v) c[m][n][v] = 0.f;
    float k2a = 0.f;                             // exact ||k||^2 for row tid

    // ---- prologue: stages 0,1 in flight ----
    issue_stage(smb, tid, keys, kBase, 0); cp_commit();
    issue_stage(smb, tid, keys, kBase, 1); cp_commit();

    // ---- mainloop: one barrier per kc ----
    for (int kc = 0; kc < NKC; ++kc) {
        cp_wait<1>();                            // stage kc complete
        __syncthreads();                         // all pack(kc-1) done; K32(kc) visible

        // MMA(kc-1) from KH((kc-1)&1)
        if (kc > 0)
            do_mma(c, aBase + ((kc - 1) & 1) * KHSTG,
                   bBase + ((kc - 1) & 3) * QSTG);

        // pack(kc): K32(kc%3) -> k2 + KH(kc&1)
        {
            const float* src = (const float*)(sm + (kc % 3) * K32STG) + tid * 36;
            const unsigned kh = smb + SMO_KH + (kc & 1) * KHSTG + tid * KHP;
            #pragma unroll
            for (int j = 0; j < 8; ++j) {
                float4 x = *(const float4*)(src + j * 4);
                k2a = fmaf(x.x, x.x, k2a); k2a = fmaf(x.y, x.y, k2a);
                k2a = fmaf(x.z, x.z, k2a); k2a = fmaf(x.w, x.w, k2a);
                sts64(kh + j * 8, cvt_h2(x.x, x.y), cvt_h2(x.z, x.w));
            }
        }

        // cp-issue(kc+2) into K32((kc+2)%3), Q((kc+2)&3)
        if (kc + 2 < NKC) issue_stage(smb, tid, keys, kBase, kc + 2);
        cp_commit();                             // uniform group counting
    }
    cp_wait<0>();
    __syncthreads();                             // last pack visible to all
    do_mma(c, aBase + ((NKC - 1) & 1) * KHSTG, bBase + ((NKC - 1) & 3) * QSTG);

    // ---- k2 to smem (row per thread; exact fp32) ----
    k2s[tid] = 0.5f * k2a;
    __syncthreads();

    // ---- decode scores to sT[query][key] ----
    #pragma unroll
    for (int m = 0; m < 2; ++m) {
        const int k0 = w * 32 + m * 16 + g;
        const float h0 = k2s[k0], h1 = k2s[k0 + 8];
        #pragma unroll
        for (int n = 0; n < 8; ++n) {
            const int q0 = n * 8 + 2 * t;
            sT[q0 * 264 + k0]           = c[m][n][0] - h0;
            sT[(q0 + 1) * 264 + k0]     = c[m][n][1] - h0;
            sT[q0 * 264 + k0 + 8]       = c[m][n][2] - h1;
            sT[(q0 + 1) * 264 + k0 + 8] = c[m][n][3] - h1;
        }
    }
    __syncthreads();

    // ---- per-query top-8 (4 threads per query) ----
    {
        const int q = tid >> 2, part = tid & 3;
        float lv[8]; int li[8];
        #pragma unroll
        for (int j = 0; j < 8; ++j) { lv[j] = -3.4e38f; li[j] = 0; }
        const float* row = sT + q * 264 + part * 64;
        #pragma unroll 4
        for (int i = 0; i < 16; ++i) {
            float4 vv = *reinterpret_cast<const float4*>(row + i * 4);
            int bidx = kBase + part * 64 + i * 4;
            float vs[4] = {vv.x, vv.y, vv.z, vv.w};
            #pragma unroll
            for (int cc = 0; cc < 4; ++cc) {
                if (vs[cc] > lv[7]) {
                    lv[7] = vs[cc]; li[7] = bidx + cc;
                    #pragma unroll
                    for (int tt = 7; tt >= 1; --tt)
                        if (lv[tt] > lv[tt - 1]) {
                            float tv = lv[tt]; lv[tt] = lv[tt - 1]; lv[tt - 1] = tv;
                            int   ti = li[tt]; li[tt] = li[tt - 1]; li[tt - 1] = ti;
                        }
                }
            }
        }
        const int sl = lane & 3;
        for (int r = 0; r < Kk; ++r) {
            float mv = lv[0]; int mi = li[0]; int ml = sl;
            #pragma unroll
            for (int off = 1; off < 4; off <<= 1) {
                float ov = __shfl_xor_sync(0xffffffffu, mv, off);
                int   oi = __shfl_xor_sync(0xffffffffu, mi, off);
                int   ol = __shfl_xor_sync(0xffffffffu, ml, off);
                if (ov > mv || (ov == mv && ol < ml)) { mv = ov; mi = oi; ml = ol; }
            }
            if (ml == sl) {
                #pragma unroll
                for (int tt = 0; tt < 7; ++tt) { lv[tt] = lv[tt + 1]; li[tt] = li[tt + 1]; }
                lv[7] = -3.4e38f;
            }
            if (sl == 0) {
                size_t o = ((size_t)q * NCHUNK + blockIdx.x) * Kk + r;
                g_cs[o] = mv; g_ci[o] = mi;
            }
        }
    }
}

// =====================================================================
// Kernel 2: global approx top-16 -> exact fp32 rescore -> top-8
// =====================================================================
__global__ __launch_bounds__(256)
void k_topk(const float* __restrict__ qh, const float* __restrict__ keys,
            const void* __restrict__ values_raw) {
    __shared__ float sval[256 * 16];
    __shared__ int   sidx[256 * 16];
    __shared__ float rv[256];
    __shared__ int   rp[256];
    __shared__ int   topi[TOPC];
    __shared__ float exacts[TOPC];
    __shared__ int   is64;

    const int b = blockIdx.x, tid = threadIdx.x;

    if (tid == 0) is64 = 1;
    __syncthreads();
    {
        const int2* vv = (const int2*)values_raw;
        int bad = 0;
        #pragma unroll
        for (int s = 0; s < 16; ++s) bad |= vv[tid + s * 256].y;
        if (bad != 0) is64 = 0;
    }

    float lv[16]; int li[16];
    #pragma unroll
    for (int j = 0; j < 16; ++j) { lv[j] = -3.4e38f; li[j] = 0; }
    const size_t base = (size_t)b * (NCHUNK * Kk);
    for (int s = 0; s < (NCHUNK * Kk) / 256; ++s) {
        int j = tid + s * 256;
        float v = g_cs[base + j];
        int  ix = g_ci[base + j];
        if (v > lv[15]) {
            lv[15] = v; li[15] = ix;
            #pragma unroll
            for (int tt = 15; tt >= 1; --tt)
                if (lv[tt] > lv[tt - 1]) {
                    float tv = lv[tt]; lv[tt] = lv[tt - 1]; lv[tt - 1] = tv;
                    int   ti = li[tt]; li[tt] = li[tt - 1]; li[tt - 1] = ti;
                }
        }
    }
    #pragma unroll
    for (int j = 0; j < 16; ++j) { sval[tid * 16 + j] = lv[j]; sidx[tid * 16 + j] = li[j]; }
    __syncthreads();

    for (int r = 0; r < TOPC; ++r) {
        float best = -3.4e38f; int bp = 0;
        #pragma unroll
        for (int s = 0; s < 16; ++s) {
            int p = tid * 16 + s;
            if (sval[p] > best) { best = sval[p]; bp = p; }
        }
        rv[tid] = best; rp[tid] = bp;
        __syncthreads();
        for (int st = 128; st > 0; st >>= 1) {
            if (tid < st && rv[tid + st] > rv[tid]) { rv[tid] = rv[tid + st]; rp[tid] = rp[tid + st]; }
            __syncthreads();
        }
        if (tid == 0) { topi[r] = sidx[rp[0]]; sval[rp[0]] = -3.4e38f; }
        __syncthreads();
    }

    // exact fp32 rescore: 16 threads per candidate
    {
        int j = tid >> 4, l = tid & 15;
        const float* kr = keys + (size_t)topi[j] * Dd;
        const float* qr = qh + (size_t)b * Dd;
        float dot = 0.f, kk = 0.f;
        for (int d = l; d < Dd; d += 16) {
            float kv = kr[d];
            dot = fmaf(qr[d], kv, dot);
            kk  = fmaf(kv, kv, kk);
        }
        #pragma unroll
        for (int off = 8; off > 0; off >>= 1) {
            dot += __shfl_xor_sync(0xffffffffu, dot, off);
            kk  += __shfl_xor_sync(0xffffffffu, kk, off);
        }
        if (l == 0) exacts[j] = dot - 0.5f * kk;
    }
    __syncthreads();

    if (tid == 0) {
        int order[Kk]; unsigned used = 0;
        for (int r = 0; r < Kk; ++r) {
            float best = -3.4e38f; int bj = 0;
            for (int j = 0; j < TOPC; ++j)
                if (!((used >> j) & 1u) && exacts[j] > best) { best = exacts[j]; bj = j; }
            used |= 1u << bj; order[r] = bj;
        }
        float m = exacts[order[0]];
        float e[Kk], se = 0.f;
        for (int r = 0; r < Kk; ++r) { e[r] = expf(2.f * (exacts[order[r]] - m) / TEMP); se += e[r]; }
        float sw = 0.f;
        for (int r = 0; r < Kk; ++r) {
            float wv = e[r] / se;
            g_w[b * Kk + r] = wv; sw += wv;
            int gi = topi[order[r]];
            int tok = is64 ? (int)((const long long*)values_raw)[gi]
                           : ((const int*)values_raw)[gi];
            g_tok[b * Kk + r] = tok;
        }
        g_sumw[b] = sw;
    }
}

// =====================================================================
// Kernel 3a: per-(row, quarter) partial max & sum(exp); 256 blocks
// =====================================================================
__global__ __launch_bounds__(256)
void k_rowstats_part(const float* __restrict__ bl) {
    __shared__ float red[8];
    __shared__ float s_bc;
    const int b = blockIdx.x >> 2, p = blockIdx.x & 3;
    const int tid = threadIdx.x;
    const int wid = tid >> 5, lid = tid & 31;
    const size_t rowoff = (size_t)b * Vv;
    const float* row = bl + rowoff;
    const int vs = (p * Vv) / 4, ve = ((p + 1) * Vv) / 4;
    const int a0 = vs + (int)((4u - (unsigned)((rowoff + vs) & 3u)) & 3u);
    const int n4 = (ve - a0) >> 2;
    const float4* rowa = (const float4*)(row + a0);

    float m = -3.4e38f;
    for (int i = tid; i < n4; i += 256) {
        float4 v = rowa[i];
        m = fmaxf(m, fmaxf(fmaxf(v.x, v.y), fmaxf(v.z, v.w)));
    }
    if (vs + tid < a0) m = fmaxf(m, row[vs + tid]);
    for (int v = a0 + 4 * n4 + tid; v < ve; v += 256) m = fmaxf(m, row[v]);
    #pragma unroll
    for (int off = 16; off > 0; off >>= 1) m = fmaxf(m, __shfl_xor_sync(0xffffffffu, m, off));
    if (lid == 0) red[wid] = m;
    __syncthreads();
    if (tid < 8) {
        float x = red[tid];
        #pragma unroll
        for (int off = 4; off > 0; off >>= 1) x = fmaxf(x, __shfl_xor_sync(0xffu, x, off));
        if (tid == 0) { s_bc = x; g_pm[b * 4 + p] = x; }
    }
    __syncthreads();
    const float rm = s_bc;

    float s = 0.f;
    for (int i = tid; i < n4; i += 256) {
        float4 v = rowa[i];
        s += expf(v.x - rm) + expf(v.y - rm) + expf(v.z - rm) + expf(v.w - rm);
    }
    if (vs + tid < a0) s += expf(row[vs + tid] - rm);
    for (int v = a0 + 4 * n4 + tid; v < ve; v += 256) s += expf(row[v] - rm);
    #pragma unroll
    for (int off = 16; off > 0; off >>= 1) s += __shfl_xor_sync(0xffffffffu, s, off);
    if (lid == 0) red[wid] = s;
    __syncthreads();
    if (tid < 8) {
        float x = red[tid];
        #pragma unroll
        for (int off = 4; off > 0; off >>= 1) x += __shfl_xor_sync(0xffu, x, off);
        if (tid == 0) g_ps[b * 4 + p] = x;
    }
}

// =====================================================================
// Kernel 3b: final mix; alignment-peeled float4 (head/tail scalar)
// =====================================================================
__global__ __launch_bounds__(256)
void k_final(const float* __restrict__ bl, float* __restrict__ out, long long out_size) {
    __shared__ float ws[Kk]; __shared__ int ts[Kk];
    __shared__ float s_rm, s_rs, s_sw;
    const int b = blockIdx.y, tid = threadIdx.x;
    if (tid < Kk) { ws[tid] = g_w[b * Kk + tid]; ts[tid] = g_tok[b * Kk + tid]; }
    if (tid == 8)  s_sw = g_sumw[b];
    if (tid == 0) {
        float m0 = fmaxf(fmaxf(g_pm[b * 4], g_pm[b * 4 + 1]),
                         fmaxf(g_pm[b * 4 + 2], g_pm[b * 4 + 3]));
        float ss = 0.f;
        #pragma unroll
        for (int i = 0; i < 4; ++i) ss += g_ps[b * 4 + i] * expf(g_pm[b * 4 + i] - m0);
        s_rm = m0; s_rs = ss;
    }
    __syncthreads();

    const float rm = s_rm, rs = s_rs;
    const float Z = s_sw + (float)Vv * EPSV;
    const size_t BV = (size_t)Bq * Vv;
    const size_t rowoff = (size_t)b * Vv;
    const int mis = (int)((4u - ((unsigned)(rowoff & 3u))) & 3u);

    auto emit = [&](int v) {
        const size_t o = rowoff + v;
        float blv = bl[o];
        float tp = 0.f;
        #pragma unroll
        for (int j = 0; j < Kk; ++j) if (ts[j] == v) tp += ws[j];
        float pk = (tp + EPSV) / Z;
        float pb = expf(blv - rm) / rs;
        float pi = (1.0f - LAM) * pb + LAM * pk;
        if ((long long)o < out_size)            out[o]          = logf(pi);
        if ((long long)(BV + o) < out_size)     out[BV + o]     = blv;
        if ((long long)(2 * BV + o) < out_size) out[2 * BV + o] = logf(tp + EPSV);
    };

    const int v4 = mis + (blockIdx.x * 256 + tid) * 4;
    if (v4 + 4 <= Vv) {
        const size_t off = rowoff + v4;
        if ((long long)(2 * BV + off + 4) <= out_size) {
            float4 blv = *(const float4*)(bl + off);
            float tp[4] = {0.f, 0.f, 0.f, 0.f};
            #pragma unroll
            for (int j = 0; j < Kk; ++j) {
                int d = ts[j] - v4;
                if ((unsigned)d < 4u) tp[d] += ws[j];
            }
            float bv[4] = {blv.x, blv.y, blv.z, blv.w};
            float4 o1, o3;
            float* o1p = &o1.x; float* o3p = &o3.x;
            #pragma unroll
            for (int cidx = 0; cidx < 4; ++cidx) {
                float pk = (tp[cidx] + EPSV) / Z;
                float pb = expf(bv[cidx] - rm) / rs;
                o1p[cidx] = logf((1.0f - LAM) * pb + LAM * pk);
                o3p[cidx] = logf(tp[cidx] + EPSV);
            }
            *(float4*)(out + off)          = o1;
            *(float4*)(out + BV + off)     = blv;
            *(float4*)(out + 2 * BV + off) = o3;
        } else {
            #pragma unroll
            for (int cidx = 0; cidx < 4; ++cidx) emit(v4 + cidx);
        }
    } else {
        for (int v = v4; v < Vv; ++v) emit(v);
    }
    if (blockIdx.x == 0 && tid < mis) emit(tid);
}

// =====================================================================
extern "C" void kernel_launch(void* const* d_in, const int* in_sizes, int n_in,
                              void* d_out, int out_size) {
    const float* qh   = (const float*)d_in[0];   // [B, D] f32
    const float* bl   = (const float*)d_in[1];   // [B, V] f32
    const float* keys = (const float*)d_in[2];   // [N, D] f32
    const void*  vals = d_in[3];                 // [N] int64 (or int32)
    float* out = (float*)d_out;

    cudaFuncSetAttribute(k_scores_f16, cudaFuncAttributeMaxDynamicSharedMemorySize, SMEM_BYTES);

    k_prepq<<<(Bq * Dd + 511) / 512, 512>>>(qh);
    k_dummy<<<1, 32>>>();                        // align ncu capture slot
    k_dummy<<<1, 32>>>();                        // (capture = 4th launch)
    k_scores_f16<<<NCHUNK, 256, SMEM_BYTES>>>(keys);
    k_topk<<<Bq, 256>>>(qh, keys, vals);
    k_rowstats_part<<<Bq * 4, 256>>>(bl);
    dim3 g3((Vv / 4 + 256) / 256, Bq);
    k_final<<<g3, 256>>>(bl, out, (long long)out_size);
}

// round 13
// speedup vs baseline: 1.1643x; 1.1643x over previous
#include <cuda_runtime.h>
#include <cuda_fp16.h>
#include <math.h>
#include <stdint.h>

// ---------------- problem constants ----------------
#define Bq   64
#define Dd   768
#define Nn   262144
#define Vv   50257
#define Kk   8
#define TEMP 10.0f
#define LAM  0.25f
#define EPSV 1e-10f

#define KPC    256                 // keys per CTA
#define NCHUNK (Nn / KPC)          // 1024
#define NKC    24                  // 768/32 d-tiles
#define TOPC   16                  // candidates rescored exactly

// smem layout (bytes)
#define K32P   128                 // K row pitch (fp32 tile; fp16 packed in place)
#define K32STG (KPC * K32P)        // 32768 per stage, 3 stages @ 0
#define QPITCH 80
#define QSTG   (64 * QPITCH)       // 5120 per Q slot (3 slots)
#define SMO_Q    (3 * K32STG)      // 98304
#define SMO_K2   (SMO_Q + 3 * QSTG)  // 113664
#define SMEM_BYTES (SMO_K2 + 1024)   // 114688  -> 2 CTAs/SM

// ---------------- scratch ----------------
__device__ float  g_cs[Bq * NCHUNK * Kk];
__device__ int    g_ci[Bq * NCHUNK * Kk];
__device__ float  g_w[Bq * Kk];
__device__ int    g_tok[Bq * Kk];
__device__ float  g_sumw[Bq];
__device__ float  g_pm[Bq * 4];
__device__ float  g_ps[Bq * 4];
__device__ __half g_qh[Bq * Dd];           // fp16 Q

// ---------------- helpers ----------------
__device__ __forceinline__ unsigned smem_u32(const void* p) {
    unsigned a;
    asm("{ .reg .u64 t; cvta.to.shared.u64 t, %1; cvt.u32.u64 %0, t; }" : "=r"(a) : "l"(p));
    return a;
}
__device__ __forceinline__ void cp16(unsigned dst, const void* src) {
    asm volatile("cp.async.cg.shared.global [%0], [%1], 16;" :: "r"(dst), "l"(src));
}
__device__ __forceinline__ void cp_commit() { asm volatile("cp.async.commit_group;" ::: "memory"); }
template<int N> __device__ __forceinline__ void cp_wait() { asm volatile("cp.async.wait_group %0;" :: "n"(N) : "memory"); }

__device__ __forceinline__ unsigned cvt_h2(float lo, float hi) {
    unsigned r;
    asm("cvt.rn.f16x2.f32 %0, %1, %2;" : "=r"(r) : "f"(hi), "f"(lo));
    return r;
}
__device__ __forceinline__ void ldm4(unsigned r[4], unsigned addr) {
    asm volatile("ldmatrix.sync.aligned.m8n8.x4.shared.b16 {%0,%1,%2,%3}, [%4];"
                 : "=r"(r[0]), "=r"(r[1]), "=r"(r[2]), "=r"(r[3]) : "r"(addr));
}
__device__ __forceinline__ float4 lds128(unsigned addr) {
    float4 v;
    asm volatile("ld.shared.v4.f32 {%0,%1,%2,%3}, [%4];"
                 : "=f"(v.x), "=f"(v.y), "=f"(v.z), "=f"(v.w) : "r"(addr));
    return v;
}
__device__ __forceinline__ void sts64(unsigned addr, unsigned w0, unsigned w1) {
    asm volatile("st.shared.v2.b32 [%0], {%1,%2};" :: "r"(addr), "r"(w0), "r"(w1));
}
__device__ __forceinline__ void mma_f16(float c[4],
                                        unsigned a0, unsigned a1, unsigned a2, unsigned a3,
                                        unsigned b0, unsigned b1) {
    asm volatile(
        "mma.sync.aligned.m16n8k16.row.col.f32.f16.f16.f32 "
        "{%0,%1,%2,%3}, {%4,%5,%6,%7}, {%8,%9}, {%0,%1,%2,%3};"
        : "+f"(c[0]), "+f"(c[1]), "+f"(c[2]), "+f"(c[3])
        : "r"(a0), "r"(a1), "r"(a2), "r"(a3), "r"(b0), "r"(b1));
}

// =====================================================================
// Dummy kernel (aligns ncu capture slot onto k_scores = 4th launch)
// =====================================================================
__global__ void k_dummy() {}

// =====================================================================
// Kernel 0: Q fp32 -> fp16 global
// =====================================================================
__global__ __launch_bounds__(512)
void k_prepq(const float* __restrict__ qh) {
    int i = blockIdx.x * 512 + threadIdx.x;
    if (i < Bq * Dd) g_qh[i] = __float2half_rn(qh[i]);
}

// =====================================================================
// Kernel 1: fp16 MMA; 3-stage fp32 K ring, fp16 packed IN PLACE,
// cp.async for kc+2 issued at TOP of iteration (wide prefetch window).
// =====================================================================
__device__ __forceinline__ void issue_stage(unsigned smb, int tid,
                                            const float* __restrict__ keys,
                                            int kBase, int kc) {
    const int r0 = tid >> 3, jw = tid & 7;
    const unsigned kdst0 = smb + (kc % 3) * K32STG + jw * 16;
    const float* ksrc0 = keys + (size_t)(kBase + r0) * Dd + kc * 32 + jw * 4;
    #pragma unroll
    for (int p = 0; p < 8; ++p)
        cp16(kdst0 + (r0 + 32 * p) * K32P, ksrc0 + (size_t)(32 * p) * Dd);
    const int qr = tid >> 2, qc = tid & 3;
    cp16(smb + SMO_Q + (kc % 3) * QSTG + qr * QPITCH + qc * 16,
         g_qh + qr * Dd + kc * 32 + qc * 8);
}

__global__ void __launch_bounds__(256, 2)
k_scores_f16(const float* __restrict__ keys) {
    extern __shared__ char sm[];
    const unsigned smb = smem_u32(sm);
    float* k2s = (float*)(sm + SMO_K2);
    float* sT  = (float*)sm;                     // 64 x 264 f32, post-mainloop

    const int tid = threadIdx.x;
    const int w = tid >> 5, lane = tid & 31;
    const int g = lane >> 2, t = lane & 3;
    const int kBase = blockIdx.x * KPC;

    // pack/cp mapping: chunk jw of rows r0 + 32p
    const int r0 = tid >> 3, jw = tid & 7;
    const unsigned packRd = r0 * K32P + jw * 16;                    // + 32p*K32P
    const unsigned packWr = r0 * K32P + (r0 & 3) * 16 + jw * 8;     // + 32p*K32P

    // ldmatrix A lane offsets (embedded fp16 rows: row*128 + (row&3)*16)
    const unsigned aRow = (lane & 7) + ((lane >> 3) & 1) * 8;
    const unsigned aCol = (lane >> 4) * 16;
    unsigned aOff[2];
    #pragma unroll
    for (int m = 0; m < 2; ++m) {
        const unsigned row = w * 32 + m * 16 + aRow;
        aOff[m] = row * K32P + (row & 3) * 16 + aCol;
    }
    // ldmatrix B lane offset (Q slots, pitch 80)
    const unsigned bRow = lane & 7;
    const unsigned bNt  = (lane >> 4) & 1;
    const unsigned bKo  = ((lane >> 3) & 1) * 16;
    const unsigned bOff = (bNt * 8 + bRow) * QPITCH + bKo;

    float c[2][8][4];
    #pragma unroll
    for (int m = 0; m < 2; ++m)
        #pragma unroll
        for (int n = 0; n < 8; ++n)
            #pragma unroll
            for (int v = 0; v < 4; ++v) c[m][n][v] = 0.f;
    float k2a[8];
    #pragma unroll
    for (int p = 0; p < 8; ++p) k2a[p] = 0.f;

    // ---- prologue: stages 0,1 in flight ----
    issue_stage(smb, tid, keys, kBase, 0); cp_commit();
    issue_stage(smb, tid, keys, kBase, 1); cp_commit();

    // ---- mainloop ----
    for (int kc = 0; kc < NKC; ++kc) {
        cp_wait<1>();                            // stage kc landed
        __syncthreads();                         // all MMA(kc-1) done

        // EARLY prefetch kc+2 -> stage (kc+2)%3 (distinct from kc%3)
        if (kc + 2 < NKC) issue_stage(smb, tid, keys, kBase, kc + 2);
        cp_commit();                             // uniform group counting

        // pack(kc) IN PLACE in stage kc%3 (2 groups of 4 row-sets)
        {
            const unsigned stg = smb + (kc % 3) * K32STG;
            #pragma unroll
            for (int h = 0; h < 2; ++h) {
                float4 x[4];
                #pragma unroll
                for (int q4 = 0; q4 < 4; ++q4)
                    x[q4] = lds128(stg + packRd + (h * 4 + q4) * 32 * K32P);
                __syncwarp();
                #pragma unroll
                for (int q4 = 0; q4 < 4; ++q4) {
                    const int p = h * 4 + q4;
                    float4 v = x[q4];
                    k2a[p] = fmaf(v.x, v.x, k2a[p]); k2a[p] = fmaf(v.y, v.y, k2a[p]);
                    k2a[p] = fmaf(v.z, v.z, k2a[p]); k2a[p] = fmaf(v.w, v.w, k2a[p]);
                    sts64(stg + packWr + p * 32 * K32P, cvt_h2(v.x, v.y), cvt_h2(v.z, v.w));
                }
            }
        }
        __syncthreads();                         // packed fp16 visible CTA-wide

        // MMA(kc)
        {
            const unsigned kst = smb + (kc % 3) * K32STG;
            const unsigned qst = smb + SMO_Q + (kc % 3) * QSTG + bOff;
            #pragma unroll
            for (int ks = 0; ks < 2; ++ks) {
                unsigned A0[4], A1[4];
                ldm4(A0, kst + aOff[0] + ks * 32);
                ldm4(A1, kst + aOff[1] + ks * 32);
                #pragma unroll
                for (int np = 0; np < 4; ++np) {
                    unsigned B[4];
                    ldm4(B, qst + np * (16 * QPITCH) + ks * 32);
                    mma_f16(c[0][2 * np],     A0[0], A0[1], A0[2], A0[3], B[0], B[1]);
                    mma_f16(c[0][2 * np + 1], A0[0], A0[1], A0[2], A0[3], B[2], B[3]);
                    mma_f16(c[1][2 * np],     A1[0], A1[1], A1[2], A1[3], B[0], B[1]);
                    mma_f16(c[1][2 * np + 1], A1[0], A1[1], A1[2], A1[3], B[2], B[3]);
                }
            }
        }
    }
    cp_wait<0>();
    __syncthreads();                             // all MMA done; buffers dead

    // ---- k2: reduce over 8 chunk-threads, write k2s ----
    #pragma unroll
    for (int p = 0; p < 8; ++p) {
        float s = k2a[p];
        #pragma unroll
        for (int off = 1; off < 8; off <<= 1) s += __shfl_xor_sync(0xffffffffu, s, off);
        if (jw == 0) k2s[r0 + 32 * p] = 0.5f * s;
    }
    __syncthreads();

    // ---- decode scores to sT[query][key] ----
    #pragma unroll
    for (int m = 0; m < 2; ++m) {
        const int k0 = w * 32 + m * 16 + g;
        const float h0 = k2s[k0], h1 = k2s[k0 + 8];
        #pragma unroll
        for (int n = 0; n < 8; ++n) {
            const int q0 = n * 8 + 2 * t;
            sT[q0 * 264 + k0]           = c[m][n][0] - h0;
            sT[(q0 + 1) * 264 + k0]     = c[m][n][1] - h0;
            sT[q0 * 264 + k0 + 8]       = c[m][n][2] - h1;
            sT[(q0 + 1) * 264 + k0 + 8] = c[m][n][3] - h1;
        }
    }
    __syncthreads();

    // ---- per-query top-8 (4 threads per query) ----
    {
        const int q = tid >> 2, part = tid & 3;
        float lv[8]; int li[8];
        #pragma unroll
        for (int j = 0; j < 8; ++j) { lv[j] = -3.4e38f; li[j] = 0; }
        const float* row = sT + q * 264 + part * 64;
        #pragma unroll 4
        for (int i = 0; i < 16; ++i) {
            float4 vv = *reinterpret_cast<const float4*>(row + i * 4);
            int bidx = kBase + part * 64 + i * 4;
            float vs[4] = {vv.x, vv.y, vv.z, vv.w};
            #pragma unroll
            for (int cc = 0; cc < 4; ++cc) {
                if (vs[cc] > lv[7]) {
                    lv[7] = vs[cc]; li[7] = bidx + cc;
                    #pragma unroll
                    for (int tt = 7; tt >= 1; --tt)
                        if (lv[tt] > lv[tt - 1]) {
                            float tv = lv[tt]; lv[tt] = lv[tt - 1]; lv[tt - 1] = tv;
                            int   ti = li[tt]; li[tt] = li[tt - 1]; li[tt - 1] = ti;
                        }
                }
            }
        }
        const int sl = lane & 3;
        for (int r = 0; r < Kk; ++r) {
            float mv = lv[0]; int mi = li[0]; int ml = sl;
            #pragma unroll
            for (int off = 1; off < 4; off <<= 1) {
                float ov = __shfl_xor_sync(0xffffffffu, mv, off);
                int   oi = __shfl_xor_sync(0xffffffffu, mi, off);
                int   ol = __shfl_xor_sync(0xffffffffu, ml, off);
                if (ov > mv || (ov == mv && ol < ml)) { mv = ov; mi = oi; ml = ol; }
            }
            if (ml == sl) {
                #pragma unroll
                for (int tt = 0; tt < 7; ++tt) { lv[tt] = lv[tt + 1]; li[tt] = li[tt + 1]; }
                lv[7] = -3.4e38f;
            }
            if (sl == 0) {
                size_t o = ((size_t)q * NCHUNK + blockIdx.x) * Kk + r;
                g_cs[o] = mv; g_ci[o] = mi;
            }
        }
    }
}

// =====================================================================
// Kernel 2: global approx top-16 -> exact fp32 rescore -> top-8
// =====================================================================
__global__ __launch_bounds__(256)
void k_topk(const float* __restrict__ qh, const float* __restrict__ keys,
            const void* __restrict__ values_raw) {
    __shared__ float sval[256 * 16];
    __shared__ int   sidx[256 * 16];
    __shared__ float rv[256];
    __shared__ int   rp[256];
    __shared__ int   topi[TOPC];
    __shared__ float exacts[TOPC];
    __shared__ int   is64;

    const int b = blockIdx.x, tid = threadIdx.x;

    if (tid == 0) is64 = 1;
    __syncthreads();
    {
        const int2* vv = (const int2*)values_raw;
        int bad = 0;
        #pragma unroll
        for (int s = 0; s < 16; ++s) bad |= vv[tid + s * 256].y;
        if (bad != 0) is64 = 0;
    }

    float lv[16]; int li[16];
    #pragma unroll
    for (int j = 0; j < 16; ++j) { lv[j] = -3.4e38f; li[j] = 0; }
    const size_t base = (size_t)b * (NCHUNK * Kk);
    for (int s = 0; s < (NCHUNK * Kk) / 256; ++s) {
        int j = tid + s * 256;
        float v = g_cs[base + j];
        int  ix = g_ci[base + j];
        if (v > lv[15]) {
            lv[15] = v; li[15] = ix;
            #pragma unroll
            for (int tt = 15; tt >= 1; --tt)
                if (lv[tt] > lv[tt - 1]) {
                    float tv = lv[tt]; lv[tt] = lv[tt - 1]; lv[tt - 1] = tv;
                    int   ti = li[tt]; li[tt] = li[tt - 1]; li[tt - 1] = ti;
                }
        }
    }
    #pragma unroll
    for (int j = 0; j < 16; ++j) { sval[tid * 16 + j] = lv[j]; sidx[tid * 16 + j] = li[j]; }
    __syncthreads();

    for (int r = 0; r < TOPC; ++r) {
        float best = -3.4e38f; int bp = 0;
        #pragma unroll
        for (int s = 0; s < 16; ++s) {
            int p = tid * 16 + s;
            if (sval[p] > best) { best = sval[p]; bp = p; }
        }
        rv[tid] = best; rp[tid] = bp;
        __syncthreads();
        for (int st = 128; st > 0; st >>= 1) {
            if (tid < st && rv[tid + st] > rv[tid]) { rv[tid] = rv[tid + st]; rp[tid] = rp[tid + st]; }
            __syncthreads();
        }
        if (tid == 0) { topi[r] = sidx[rp[0]]; sval[rp[0]] = -3.4e38f; }
        __syncthreads();
    }

    // exact fp32 rescore: 16 threads per candidate
    {
        int j = tid >> 4, l = tid & 15;
        const float* kr = keys + (size_t)topi[j] * Dd;
        const float* qr = qh + (size_t)b * Dd;
        float dot = 0.f, kk = 0.f;
        for (int d = l; d < Dd; d += 16) {
            float kv = kr[d];
            dot = fmaf(qr[d], kv, dot);
            kk  = fmaf(kv, kv, kk);
        }
        #pragma unroll
        for (int off = 8; off > 0; off >>= 1) {
            dot += __shfl_xor_sync(0xffffffffu, dot, off);
            kk  += __shfl_xor_sync(0xffffffffu, kk, off);
        }
        if (l == 0) exacts[j] = dot - 0.5f * kk;
    }
    __syncthreads();

    if (tid == 0) {
        int order[Kk]; unsigned used = 0;
        for (int r = 0; r < Kk; ++r) {
            float best = -3.4e38f; int bj = 0;
            for (int j = 0; j < TOPC; ++j)
                if (!((used >> j) & 1u) && exacts[j] > best) { best = exacts[j]; bj = j; }
            used |= 1u << bj; order[r] = bj;
        }
        float m = exacts[order[0]];
        float e[Kk], se = 0.f;
        for (int r = 0; r < Kk; ++r) { e[r] = expf(2.f * (exacts[order[r]] - m) / TEMP); se += e[r]; }
        float sw = 0.f;
        for (int r = 0; r < Kk; ++r) {
            float wv = e[r] / se;
            g_w[b * Kk + r] = wv; sw += wv;
            int gi = topi[order[r]];
            int tok = is64 ? (int)((const long long*)values_raw)[gi]
                           : ((const int*)values_raw)[gi];
            g_tok[b * Kk + r] = tok;
        }
        g_sumw[b] = sw;
    }
}

// =====================================================================
// Kernel 3a: per-(row, quarter) partial max & sum(exp); 256 blocks
// =====================================================================
__global__ __launch_bounds__(256)
void k_rowstats_part(const float* __restrict__ bl) {
    __shared__ float red[8];
    __shared__ float s_bc;
    const int b = blockIdx.x >> 2, p = blockIdx.x & 3;
    const int tid = threadIdx.x;
    const int wid = tid >> 5, lid = tid & 31;
    const size_t rowoff = (size_t)b * Vv;
    const float* row = bl + rowoff;
    const int vs = (p * Vv) / 4, ve = ((p + 1) * Vv) / 4;
    const int a0 = vs + (int)((4u - (unsigned)((rowoff + vs) & 3u)) & 3u);
    const int n4 = (ve - a0) >> 2;
    const float4* rowa = (const float4*)(row + a0);

    float m = -3.4e38f;
    for (int i = tid; i < n4; i += 256) {
        float4 v = rowa[i];
        m = fmaxf(m, fmaxf(fmaxf(v.x, v.y), fmaxf(v.z, v.w)));
    }
    if (vs + tid < a0) m = fmaxf(m, row[vs + tid]);
    for (int v = a0 + 4 * n4 + tid; v < ve; v += 256) m = fmaxf(m, row[v]);
    #pragma unroll
    for (int off = 16; off > 0; off >>= 1) m = fmaxf(m, __shfl_xor_sync(0xffffffffu, m, off));
    if (lid == 0) red[wid] = m;
    __syncthreads();
    if (tid < 8) {
        float x = red[tid];
        #pragma unroll
        for (int off = 4; off > 0; off >>= 1) x = fmaxf(x, __shfl_xor_sync(0xffu, x, off));
        if (tid == 0) { s_bc = x; g_pm[b * 4 + p] = x; }
    }
    __syncthreads();
    const float rm = s_bc;

    float s = 0.f;
    for (int i = tid; i < n4; i += 256) {
        float4 v = rowa[i];
        s += expf(v.x - rm) + expf(v.y - rm) + expf(v.z - rm) + expf(v.w - rm);
    }
    if (vs + tid < a0) s += expf(row[vs + tid] - rm);
    for (int v = a0 + 4 * n4 + tid; v < ve; v += 256) s += expf(row[v] - rm);
    #pragma unroll
    for (int off = 16; off > 0; off >>= 1) s += __shfl_xor_sync(0xffffffffu, s, off);
    if (lid == 0) red[wid] = s;
    __syncthreads();
    if (tid < 8) {
        float x = red[tid];
        #pragma unroll
        for (int off = 4; off > 0; off >>= 1) x += __shfl_xor_sync(0xffu, x, off);
        if (tid == 0) g_ps[b * 4 + p] = x;
    }
}

// =====================================================================
// Kernel 3b: final mix; alignment-peeled float4 (head/tail scalar)
// =====================================================================
__global__ __launch_bounds__(256)
void k_final(const float* __restrict__ bl, float* __restrict__ out, long long out_size) {
    __shared__ float ws[Kk]; __shared__ int ts[Kk];
    __shared__ float s_rm, s_rs, s_sw;
    const int b = blockIdx.y, tid = threadIdx.x;
    if (tid < Kk) { ws[tid] = g_w[b * Kk + tid]; ts[tid] = g_tok[b * Kk + tid]; }
    if (tid == 8)  s_sw = g_sumw[b];
    if (tid == 0) {
        float m0 = fmaxf(fmaxf(g_pm[b * 4], g_pm[b * 4 + 1]),
                         fmaxf(g_pm[b * 4 + 2], g_pm[b * 4 + 3]));
        float ss = 0.f;
        #pragma unroll
        for (int i = 0; i < 4; ++i) ss += g_ps[b * 4 + i] * expf(g_pm[b * 4 + i] - m0);
        s_rm = m0; s_rs = ss;
    }
    __syncthreads();

    const float rm = s_rm, rs = s_rs;
    const float Z = s_sw + (float)Vv * EPSV;
    const size_t BV = (size_t)Bq * Vv;
    const size_t rowoff = (size_t)b * Vv;
    const int mis = (int)((4u - ((unsigned)(rowoff & 3u))) & 3u);

    auto emit = [&](int v) {
        const size_t o = rowoff + v;
        float blv = bl[o];
        float tp = 0.f;
        #pragma unroll
        for (int j = 0; j < Kk; ++j) if (ts[j] == v) tp += ws[j];
        float pk = (tp + EPSV) / Z;
        float pb = expf(blv - rm) / rs;
        float pi = (1.0f - LAM) * pb + LAM * pk;
        if ((long long)o < out_size)            out[o]          = logf(pi);
        if ((long long)(BV + o) < out_size)     out[BV + o]     = blv;
        if ((long long)(2 * BV + o) < out_size) out[2 * BV + o] = logf(tp + EPSV);
    };

    const int v4 = mis + (blockIdx.x * 256 + tid) * 4;
    if (v4 + 4 <= Vv) {
        const size_t off = rowoff + v4;
        if ((long long)(2 * BV + off + 4) <= out_size) {
            float4 blv = *(const float4*)(bl + off);
            float tp[4] = {0.f, 0.f, 0.f, 0.f};
            #pragma unroll
            for (int j = 0; j < Kk; ++j) {
                int d = ts[j] - v4;
                if ((unsigned)d < 4u) tp[d] += ws[j];
            }
            float bv[4] = {blv.x, blv.y, blv.z, blv.w};
            float4 o1, o3;
            float* o1p = &o1.x; float* o3p = &o3.x;
            #pragma unroll
            for (int cidx = 0; cidx < 4; ++cidx) {
                float pk = (tp[cidx] + EPSV) / Z;
                float pb = expf(bv[cidx] - rm) / rs;
                o1p[cidx] = logf((1.0f - LAM) * pb + LAM * pk);
                o3p[cidx] = logf(tp[cidx] + EPSV);
            }
            *(float4*)(out + off)          = o1;
            *(float4*)(out + BV + off)     = blv;
            *(float4*)(out + 2 * BV + off) = o3;
        } else {
            #pragma unroll
            for (int cidx = 0; cidx < 4; ++cidx) emit(v4 + cidx);
        }
    } else {
        for (int v = v4; v < Vv; ++v) emit(v);
    }
    if (blockIdx.x == 0 && tid < mis) emit(tid);
}

// =====================================================================
extern "C" void kernel_launch(void* const* d_in, const int* in_sizes, int n_in,
                              void* d_out, int out_size) {
    const float* qh   = (const float*)d_in[0];   // [B, D] f32
    const float* bl   = (const float*)d_in[1];   // [B, V] f32
    const float* keys = (const float*)d_in[2];   // [N, D] f32
    const void*  vals = d_in[3];                 // [N] int64 (or int32)
    float* out = (float*)d_out;

    cudaFuncSetAttribute(k_scores_f16, cudaFuncAttributeMaxDynamicSharedMemorySize, SMEM_BYTES);

    k_prepq<<<(Bq * Dd + 511) / 512, 512>>>(qh);
    k_dummy<<<1, 32>>>();                        // align ncu capture slot
    k_dummy<<<1, 32>>>();                        // (capture = 4th launch)
    k_scores_f16<<<NCHUNK, 256, SMEM_BYTES>>>(keys);
    k_topk<<<Bq, 256>>>(qh, keys, vals);
    k_rowstats_part<<<Bq * 4, 256>>>(bl);
    dim3 g3((Vv / 4 + 256) / 256, Bq);
    k_final<<<g3, 256>>>(bl, out, (long long)out_size);
}

// round 14
// speedup vs baseline: 1.2281x; 1.0549x over previous
#include <cuda_runtime.h>
#include <cuda_fp16.h>
#include <math.h>
#include <stdint.h>

// ---------------- problem constants ----------------
#define Bq   64
#define Dd   768
#define Nn   262144
#define Vv   50257
#define Kk   8
#define TEMP 10.0f
#define LAM  0.25f
#define EPSV 1e-10f

#define KPC    256                 // keys per CTA
#define NCHUNK (Nn / KPC)          // 1024
#define NKC    24                  // 768/32 d-tiles
#define TOPC   16                  // candidates rescored exactly

// smem layout (bytes)
#define K32P   128                 // K row pitch (fp32 tile; fp16 packed in place)
#define K32STG (KPC * K32P)        // 32768 per stage, 3 stages @ 0
#define QPITCH 80
#define QSTG   (64 * QPITCH)       // 5120 per Q slot (3 slots)
#define SMO_Q    (3 * K32STG)      // 98304
#define SMO_K2   (SMO_Q + 3 * QSTG)  // 113664
#define SMEM_BYTES (SMO_K2 + 1024)   // 114688  -> 2 CTAs/SM

// ---------------- scratch ----------------
__device__ float  g_cs[Bq * NCHUNK * Kk];
__device__ int    g_ci[Bq * NCHUNK * Kk];
__device__ float  g_w[Bq * Kk];
__device__ int    g_tok[Bq * Kk];
__device__ float  g_sumw[Bq];
__device__ float  g_pm[Bq * 4];
__device__ float  g_ps[Bq * 4];
__device__ __half g_qh[Bq * Dd];           // fp16 Q

// ---------------- helpers ----------------
__device__ __forceinline__ unsigned smem_u32(const void* p) {
    unsigned a;
    asm("{ .reg .u64 t; cvta.to.shared.u64 t, %1; cvt.u32.u64 %0, t; }" : "=r"(a) : "l"(p));
    return a;
}
__device__ __forceinline__ void cp16(unsigned dst, const void* src) {
    asm volatile("cp.async.cg.shared.global [%0], [%1], 16;" :: "r"(dst), "l"(src));
}
__device__ __forceinline__ void cp_commit() { asm volatile("cp.async.commit_group;" ::: "memory"); }
template<int N> __device__ __forceinline__ void cp_wait() { asm volatile("cp.async.wait_group %0;" :: "n"(N) : "memory"); }

__device__ __forceinline__ unsigned cvt_h2(float lo, float hi) {
    unsigned r;
    asm("cvt.rn.f16x2.f32 %0, %1, %2;" : "=r"(r) : "f"(hi), "f"(lo));
    return r;
}
__device__ __forceinline__ void ldm4(unsigned r[4], unsigned addr) {
    asm volatile("ldmatrix.sync.aligned.m8n8.x4.shared.b16 {%0,%1,%2,%3}, [%4];"
                 : "=r"(r[0]), "=r"(r[1]), "=r"(r[2]), "=r"(r[3]) : "r"(addr));
}
__device__ __forceinline__ float4 lds128(unsigned addr) {
    float4 v;
    asm volatile("ld.shared.v4.f32 {%0,%1,%2,%3}, [%4];"
                 : "=f"(v.x), "=f"(v.y), "=f"(v.z), "=f"(v.w) : "r"(addr));
    return v;
}
__device__ __forceinline__ void sts64(unsigned addr, unsigned w0, unsigned w1) {
    asm volatile("st.shared.v2.b32 [%0], {%1,%2};" :: "r"(addr), "r"(w0), "r"(w1));
}
__device__ __forceinline__ void mma_f16(float c[4],
                                        unsigned a0, unsigned a1, unsigned a2, unsigned a3,
                                        unsigned b0, unsigned b1) {
    asm volatile(
        "mma.sync.aligned.m16n8k16.row.col.f32.f16.f16.f32 "
        "{%0,%1,%2,%3}, {%4,%5,%6,%7}, {%8,%9}, {%0,%1,%2,%3};"
        : "+f"(c[0]), "+f"(c[1]), "+f"(c[2]), "+f"(c[3])
        : "r"(a0), "r"(a1), "r"(a2), "r"(a3), "r"(b0), "r"(b1));
}

// =====================================================================
// Kernel 0 (fused): blocks [0,256) = per-(row,quarter) softmax stats;
//                   blocks [256,280) = Q fp32 -> fp16
// =====================================================================
__global__ __launch_bounds__(256)
void k_pre(const float* __restrict__ qh, const float* __restrict__ bl) {
    if (blockIdx.x >= 256) {
        int i = (blockIdx.x - 256) * 256 + threadIdx.x;
        #pragma unroll
        for (int s = 0; s < 8; ++s) {
            g_qh[i] = __float2half_rn(qh[i]);
            i += 24 * 256;
        }
        return;
    }
    __shared__ float red[8];
    __shared__ float s_bc;
    const int b = blockIdx.x >> 2, p = blockIdx.x & 3;
    const int tid = threadIdx.x;
    const int wid = tid >> 5, lid = tid & 31;
    const size_t rowoff = (size_t)b * Vv;
    const float* row = bl + rowoff;
    const int vs = (p * Vv) / 4, ve = ((p + 1) * Vv) / 4;
    const int a0 = vs + (int)((4u - (unsigned)((rowoff + vs) & 3u)) & 3u);
    const int n4 = (ve - a0) >> 2;
    const float4* rowa = (const float4*)(row + a0);

    float m = -3.4e38f;
    for (int i = tid; i < n4; i += 256) {
        float4 v = rowa[i];
        m = fmaxf(m, fmaxf(fmaxf(v.x, v.y), fmaxf(v.z, v.w)));
    }
    if (vs + tid < a0) m = fmaxf(m, row[vs + tid]);
    for (int v = a0 + 4 * n4 + tid; v < ve; v += 256) m = fmaxf(m, row[v]);
    #pragma unroll
    for (int off = 16; off > 0; off >>= 1) m = fmaxf(m, __shfl_xor_sync(0xffffffffu, m, off));
    if (lid == 0) red[wid] = m;
    __syncthreads();
    if (tid < 8) {
        float x = red[tid];
        #pragma unroll
        for (int off = 4; off > 0; off >>= 1) x = fmaxf(x, __shfl_xor_sync(0xffu, x, off));
        if (tid == 0) { s_bc = x; g_pm[b * 4 + p] = x; }
    }
    __syncthreads();
    const float rm = s_bc;

    float s = 0.f;
    for (int i = tid; i < n4; i += 256) {
        float4 v = rowa[i];
        s += expf(v.x - rm) + expf(v.y - rm) + expf(v.z - rm) + expf(v.w - rm);
    }
    if (vs + tid < a0) s += expf(row[vs + tid] - rm);
    for (int v = a0 + 4 * n4 + tid; v < ve; v += 256) s += expf(row[v] - rm);
    #pragma unroll
    for (int off = 16; off > 0; off >>= 1) s += __shfl_xor_sync(0xffffffffu, s, off);
    if (lid == 0) red[wid] = s;
    __syncthreads();
    if (tid < 8) {
        float x = red[tid];
        #pragma unroll
        for (int off = 4; off > 0; off >>= 1) x += __shfl_xor_sync(0xffu, x, off);
        if (tid == 0) g_ps[b * 4 + p] = x;
    }
}

// =====================================================================
// Kernel 1: fp16 MMA; 3-stage fp32 K ring, fp16 packed IN PLACE,
// cp.async for kc+2 issued at TOP of iteration. (rd13 verbatim)
// =====================================================================
__device__ __forceinline__ void issue_stage(unsigned smb, int tid,
                                            const float* __restrict__ keys,
                                            int kBase, int kc) {
    const int r0 = tid >> 3, jw = tid & 7;
    const unsigned kdst0 = smb + (kc % 3) * K32STG + jw * 16;
    const float* ksrc0 = keys + (size_t)(kBase + r0) * Dd + kc * 32 + jw * 4;
    #pragma unroll
    for (int p = 0; p < 8; ++p)
        cp16(kdst0 + (r0 + 32 * p) * K32P, ksrc0 + (size_t)(32 * p) * Dd);
    const int qr = tid >> 2, qc = tid & 3;
    cp16(smb + SMO_Q + (kc % 3) * QSTG + qr * QPITCH + qc * 16,
         g_qh + qr * Dd + kc * 32 + qc * 8);
}

__global__ void __launch_bounds__(256, 2)
k_scores_f16(const float* __restrict__ keys) {
    extern __shared__ char sm[];
    const unsigned smb = smem_u32(sm);
    float* k2s = (float*)(sm + SMO_K2);
    float* sT  = (float*)sm;                     // 64 x 264 f32, post-mainloop

    const int tid = threadIdx.x;
    const int w = tid >> 5, lane = tid & 31;
    const int g = lane >> 2, t = lane & 3;
    const int kBase = blockIdx.x * KPC;

    const int r0 = tid >> 3, jw = tid & 7;
    const unsigned packRd = r0 * K32P + jw * 16;
    const unsigned packWr = r0 * K32P + (r0 & 3) * 16 + jw * 8;

    const unsigned aRow = (lane & 7) + ((lane >> 3) & 1) * 8;
    const unsigned aCol = (lane >> 4) * 16;
    unsigned aOff[2];
    #pragma unroll
    for (int m = 0; m < 2; ++m) {
        const unsigned row = w * 32 + m * 16 + aRow;
        aOff[m] = row * K32P + (row & 3) * 16 + aCol;
    }
    const unsigned bRow = lane & 7;
    const unsigned bNt  = (lane >> 4) & 1;
    const unsigned bKo  = ((lane >> 3) & 1) * 16;
    const unsigned bOff = (bNt * 8 + bRow) * QPITCH + bKo;

    float c[2][8][4];
    #pragma unroll
    for (int m = 0; m < 2; ++m)
        #pragma unroll
        for (int n = 0; n < 8; ++n)
            #pragma unroll
            for (int v = 0; v < 4; ++v) c[m][n][v] = 0.f;
    float k2a[8];
    #pragma unroll
    for (int p = 0; p < 8; ++p) k2a[p] = 0.f;

    issue_stage(smb, tid, keys, kBase, 0); cp_commit();
    issue_stage(smb, tid, keys, kBase, 1); cp_commit();

    for (int kc = 0; kc < NKC; ++kc) {
        cp_wait<1>();
        __syncthreads();

        if (kc + 2 < NKC) issue_stage(smb, tid, keys, kBase, kc + 2);
        cp_commit();

        {
            const unsigned stg = smb + (kc % 3) * K32STG;
            #pragma unroll
            for (int h = 0; h < 2; ++h) {
                float4 x[4];
                #pragma unroll
                for (int q4 = 0; q4 < 4; ++q4)
                    x[q4] = lds128(stg + packRd + (h * 4 + q4) * 32 * K32P);
                __syncwarp();
                #pragma unroll
                for (int q4 = 0; q4 < 4; ++q4) {
                    const int p = h * 4 + q4;
                    float4 v = x[q4];
                    k2a[p] = fmaf(v.x, v.x, k2a[p]); k2a[p] = fmaf(v.y, v.y, k2a[p]);
                    k2a[p] = fmaf(v.z, v.z, k2a[p]); k2a[p] = fmaf(v.w, v.w, k2a[p]);
                    sts64(stg + packWr + p * 32 * K32P, cvt_h2(v.x, v.y), cvt_h2(v.z, v.w));
                }
            }
        }
        __syncthreads();

        {
            const unsigned kst = smb + (kc % 3) * K32STG;
            const unsigned qst = smb + SMO_Q + (kc % 3) * QSTG + bOff;
            #pragma unroll
            for (int ks = 0; ks < 2; ++ks) {
                unsigned A0[4], A1[4];
                ldm4(A0, kst + aOff[0] + ks * 32);
                ldm4(A1, kst + aOff[1] + ks * 32);
                #pragma unroll
                for (int np = 0; np < 4; ++np) {
                    unsigned B[4];
                    ldm4(B, qst + np * (16 * QPITCH) + ks * 32);
                    mma_f16(c[0][2 * np],     A0[0], A0[1], A0[2], A0[3], B[0], B[1]);
                    mma_f16(c[0][2 * np + 1], A0[0], A0[1], A0[2], A0[3], B[2], B[3]);
                    mma_f16(c[1][2 * np],     A1[0], A1[1], A1[2], A1[3], B[0], B[1]);
                    mma_f16(c[1][2 * np + 1], A1[0], A1[1], A1[2], A1[3], B[2], B[3]);
                }
            }
        }
    }
    cp_wait<0>();
    __syncthreads();

    #pragma unroll
    for (int p = 0; p < 8; ++p) {
        float s = k2a[p];
        #pragma unroll
        for (int off = 1; off < 8; off <<= 1) s += __shfl_xor_sync(0xffffffffu, s, off);
        if (jw == 0) k2s[r0 + 32 * p] = 0.5f * s;
    }
    __syncthreads();

    #pragma unroll
    for (int m = 0; m < 2; ++m) {
        const int k0 = w * 32 + m * 16 + g;
        const float h0 = k2s[k0], h1 = k2s[k0 + 8];
        #pragma unroll
        for (int n = 0; n < 8; ++n) {
            const int q0 = n * 8 + 2 * t;
            sT[q0 * 264 + k0]           = c[m][n][0] - h0;
            sT[(q0 + 1) * 264 + k0]     = c[m][n][1] - h0;
            sT[q0 * 264 + k0 + 8]       = c[m][n][2] - h1;
            sT[(q0 + 1) * 264 + k0 + 8] = c[m][n][3] - h1;
        }
    }
    __syncthreads();

    {
        const int q = tid >> 2, part = tid & 3;
        float lv[8]; int li[8];
        #pragma unroll
        for (int j = 0; j < 8; ++j) { lv[j] = -3.4e38f; li[j] = 0; }
        const float* row = sT + q * 264 + part * 64;
        #pragma unroll 4
        for (int i = 0; i < 16; ++i) {
            float4 vv = *reinterpret_cast<const float4*>(row + i * 4);
            int bidx = kBase + part * 64 + i * 4;
            float vs[4] = {vv.x, vv.y, vv.z, vv.w};
            #pragma unroll
            for (int cc = 0; cc < 4; ++cc) {
                if (vs[cc] > lv[7]) {
                    lv[7] = vs[cc]; li[7] = bidx + cc;
                    #pragma unroll
                    for (int tt = 7; tt >= 1; --tt)
                        if (lv[tt] > lv[tt - 1]) {
                            float tv = lv[tt]; lv[tt] = lv[tt - 1]; lv[tt - 1] = tv;
                            int   ti = li[tt]; li[tt] = li[tt - 1]; li[tt - 1] = ti;
                        }
                }
            }
        }
        const int sl = lane & 3;
        for (int r = 0; r < Kk; ++r) {
            float mv = lv[0]; int mi = li[0]; int ml = sl;
            #pragma unroll
            for (int off = 1; off < 4; off <<= 1) {
                float ov = __shfl_xor_sync(0xffffffffu, mv, off);
                int   oi = __shfl_xor_sync(0xffffffffu, mi, off);
                int   ol = __shfl_xor_sync(0xffffffffu, ml, off);
                if (ov > mv || (ov == mv && ol < ml)) { mv = ov; mi = oi; ml = ol; }
            }
            if (ml == sl) {
                #pragma unroll
                for (int tt = 0; tt < 7; ++tt) { lv[tt] = lv[tt + 1]; li[tt] = li[tt + 1]; }
                lv[7] = -3.4e38f;
            }
            if (sl == 0) {
                size_t o = ((size_t)q * NCHUNK + blockIdx.x) * Kk + r;
                g_cs[o] = mv; g_ci[o] = mi;
            }
        }
    }
}

// =====================================================================
// Kernel 2: register-sorted pop-max top-16 -> exact fp32 rescore -> top-8
// =====================================================================
__global__ __launch_bounds__(256)
void k_topk(const float* __restrict__ qh, const float* __restrict__ keys,
            const void* __restrict__ values_raw) {
    __shared__ float sv[16 * 256];        // transposed sorted lists
    __shared__ int   si[16 * 256];
    __shared__ float wval[8];
    __shared__ int   wtid[8];
    __shared__ int   s_win;
    __shared__ int   topi[TOPC];
    __shared__ float exacts[TOPC];
    __shared__ int   is64;

    const int b = blockIdx.x, tid = threadIdx.x;
    const int wid = tid >> 5, lid = tid & 31;

    if (tid == 0) is64 = 1;
    __syncthreads();
    {
        const int2* vv = (const int2*)values_raw;
        int bad = 0;
        #pragma unroll
        for (int s = 0; s < 16; ++s) bad |= vv[tid + s * 256].y;
        if (bad != 0) is64 = 0;
    }

    // local top-16 (sorted descending) over 32 strided candidates
    float lv[16]; int li[16];
    #pragma unroll
    for (int j = 0; j < 16; ++j) { lv[j] = -3.4e38f; li[j] = 0; }
    const size_t base = (size_t)b * (NCHUNK * Kk);
    for (int s = 0; s < 32; ++s) {
        int j = tid + s * 256;
        float v = g_cs[base + j];
        int  ix = g_ci[base + j];
        if (v > lv[15]) {
            lv[15] = v; li[15] = ix;
            #pragma unroll
            for (int tt = 15; tt >= 1; --tt)
                if (lv[tt] > lv[tt - 1]) {
                    float tv = lv[tt]; lv[tt] = lv[tt - 1]; lv[tt - 1] = tv;
                    int   ti = li[tt]; li[tt] = li[tt - 1]; li[tt - 1] = ti;
                }
        }
    }
    #pragma unroll
    for (int j = 0; j < 16; ++j) { sv[j * 256 + tid] = lv[j]; si[j * 256 + tid] = li[j]; }

    // pop-max: 16 rounds; heads tracked in registers
    int   cur = 0;
    float curval = lv[0];
    for (int r = 0; r < TOPC; ++r) {
        float v = curval; int who = tid;
        #pragma unroll
        for (int off = 16; off > 0; off >>= 1) {
            float ov = __shfl_xor_sync(0xffffffffu, v, off);
            int   ow = __shfl_xor_sync(0xffffffffu, who, off);
            if (ov > v || (ov == v && ow < who)) { v = ov; who = ow; }
        }
        if (lid == 0) { wval[wid] = v; wtid[wid] = who; }
        __syncthreads();
        if (tid == 0) {
            float bv = wval[0]; int bw = wtid[0];
            #pragma unroll
            for (int i = 1; i < 8; ++i)
                if (wval[i] > bv || (wval[i] == bv && wtid[i] < bw)) { bv = wval[i]; bw = wtid[i]; }
            s_win = bw;
        }
        __syncthreads();
        if (tid == s_win) {
            topi[r] = si[cur * 256 + tid];
            ++cur;
            curval = (cur < 16) ? sv[cur * 256 + tid] : -3.4e38f;
        }
        __syncthreads();
    }

    // exact fp32 rescore: 16 threads per candidate
    {
        int j = tid >> 4, l = tid & 15;
        const float* kr = keys + (size_t)topi[j] * Dd;
        const float* qr = qh + (size_t)b * Dd;
        float dot = 0.f, kk = 0.f;
        for (int d = l; d < Dd; d += 16) {
            float kv = kr[d];
            dot = fmaf(qr[d], kv, dot);
            kk  = fmaf(kv, kv, kk);
        }
        #pragma unroll
        for (int off = 8; off > 0; off >>= 1) {
            dot += __shfl_xor_sync(0xffffffffu, dot, off);
            kk  += __shfl_xor_sync(0xffffffffu, kk, off);
        }
        if (l == 0) exacts[j] = dot - 0.5f * kk;
    }
    __syncthreads();

    if (tid == 0) {
        int order[Kk]; unsigned used = 0;
        for (int r = 0; r < Kk; ++r) {
            float best = -3.4e38f; int bj = 0;
            for (int j = 0; j < TOPC; ++j)
                if (!((used >> j) & 1u) && exacts[j] > best) { best = exacts[j]; bj = j; }
            used |= 1u << bj; order[r] = bj;
        }
        float m = exacts[order[0]];
        float e[Kk], se = 0.f;
        for (int r = 0; r < Kk; ++r) { e[r] = expf(2.f * (exacts[order[r]] - m) / TEMP); se += e[r]; }
        float sw = 0.f;
        for (int r = 0; r < Kk; ++r) {
            float wv = e[r] / se;
            g_w[b * Kk + r] = wv; sw += wv;
            int gi = topi[order[r]];
            int tok = is64 ? (int)((const long long*)values_raw)[gi]
                           : ((const int*)values_raw)[gi];
            g_tok[b * Kk + r] = tok;
        }
        g_sumw[b] = sw;
    }
}

// =====================================================================
// Kernel 3: final mix; alignment-peeled float4 (head/tail scalar)
// =====================================================================
__global__ __launch_bounds__(256)
void k_final(const float* __restrict__ bl, float* __restrict__ out, long long out_size) {
    __shared__ float ws[Kk]; __shared__ int ts[Kk];
    __shared__ float s_rm, s_rs, s_sw;
    const int b = blockIdx.y, tid = threadIdx.x;
    if (tid < Kk) { ws[tid] = g_w[b * Kk + tid]; ts[tid] = g_tok[b * Kk + tid]; }
    if (tid == 8)  s_sw = g_sumw[b];
    if (tid == 0) {
        float m0 = fmaxf(fmaxf(g_pm[b * 4], g_pm[b * 4 + 1]),
                         fmaxf(g_pm[b * 4 + 2], g_pm[b * 4 + 3]));
        float ss = 0.f;
        #pragma unroll
        for (int i = 0; i < 4; ++i) ss += g_ps[b * 4 + i] * expf(g_pm[b * 4 + i] - m0);
        s_rm = m0; s_rs = ss;
    }
    __syncthreads();

    const float rm = s_rm, rs = s_rs;
    const float Z = s_sw + (float)Vv * EPSV;
    const size_t BV = (size_t)Bq * Vv;
    const size_t rowoff = (size_t)b * Vv;
    const int mis = (int)((4u - ((unsigned)(rowoff & 3u))) & 3u);

    auto emit = [&](int v) {
        const size_t o = rowoff + v;
        float blv = bl[o];
        float tp = 0.f;
        #pragma unroll
        for (int j = 0; j < Kk; ++j) if (ts[j] == v) tp += ws[j];
        float pk = (tp + EPSV) / Z;
        float pb = expf(blv - rm) / rs;
        float pi = (1.0f - LAM) * pb + LAM * pk;
        if ((long long)o < out_size)            out[o]          = logf(pi);
        if ((long long)(BV + o) < out_size)     out[BV + o]     = blv;
        if ((long long)(2 * BV + o) < out_size) out[2 * BV + o] = logf(tp + EPSV);
    };

    const int v4 = mis + (blockIdx.x * 256 + tid) * 4;
    if (v4 + 4 <= Vv) {
        const size_t off = rowoff + v4;
        if ((long long)(2 * BV + off + 4) <= out_size) {
            float4 blv = *(const float4*)(bl + off);
            float tp[4] = {0.f, 0.f, 0.f, 0.f};
            #pragma unroll
            for (int j = 0; j < Kk; ++j) {
                int d = ts[j] - v4;
                if ((unsigned)d < 4u) tp[d] += ws[j];
            }
            float bv[4] = {blv.x, blv.y, blv.z, blv.w};
            float4 o1, o3;
            float* o1p = &o1.x; float* o3p = &o3.x;
            #pragma unroll
            for (int cidx = 0; cidx < 4; ++cidx) {
                float pk = (tp[cidx] + EPSV) / Z;
                float pb = expf(bv[cidx] - rm) / rs;
                o1p[cidx] = logf((1.0f - LAM) * pb + LAM * pk);
                o3p[cidx] = logf(tp[cidx] + EPSV);
            }
            *(float4*)(out + off)          = o1;
            *(float4*)(out + BV + off)     = blv;
            *(float4*)(out + 2 * BV + off) = o3;
        } else {
            #pragma unroll
            for (int cidx = 0; cidx < 4; ++cidx) emit(v4 + cidx);
        }
    } else {
        for (int v = v4; v < Vv; ++v) emit(v);
    }
    if (blockIdx.x == 0 && tid < mis) emit(tid);
}

// =====================================================================
extern "C" void kernel_launch(void* const* d_in, const int* in_sizes, int n_in,
                              void* d_out, int out_size) {
    const float* qh   = (const float*)d_in[0];   // [B, D] f32
    const float* bl   = (const float*)d_in[1];   // [B, V] f32
    const float* keys = (const float*)d_in[2];   // [N, D] f32
    const void*  vals = d_in[3];                 // [N] int64 (or int32)
    float* out = (float*)d_out;

    cudaFuncSetAttribute(k_scores_f16, cudaFuncAttributeMaxDynamicSharedMemorySize, SMEM_BYTES);

    k_pre<<<280, 256>>>(qh, bl);
    k_scores_f16<<<NCHUNK, 256, SMEM_BYTES>>>(keys);
    k_topk<<<Bq, 256>>>(qh, keys, vals);
    dim3 g3((Vv / 4 + 256) / 256, Bq);
    k_final<<<g3, 256>>>(bl, out, (long long)out_size);
}

// round 16
// speedup vs baseline: 1.2379x; 1.0079x over previous
#include <cuda_runtime.h>
#include <cuda_fp16.h>
#include <math.h>
#include <stdint.h>

// ---------------- problem constants ----------------
#define Bq   64
#define Dd   768
#define Nn   262144
#define Vv   50257
#define Kk   8
#define TEMP 10.0f
#define LAM  0.25f
#define EPSV 1e-10f

#define KPC    256                 // keys per CTA
#define NCHUNK (Nn / KPC)          // 1024
#define NKC    24                  // 768/32 d-tiles
#define TOPC   16                  // candidates rescored exactly

// smem layout (bytes)
#define K32P   128                 // K row pitch (fp32 tile; fp16 packed in place)
#define K32STG (KPC * K32P)        // 32768 per stage, 3 stages @ 0
#define QPITCH 80
#define QSTG   (64 * QPITCH)       // 5120 per Q slot (3 slots)
#define SMO_Q    (3 * K32STG)      // 98304
#define SMO_K2   (SMO_Q + 3 * QSTG)  // 113664
#define SMEM_BYTES (SMO_K2 + 1024)   // 114688  -> 2 CTAs/SM

// ---------------- scratch ----------------
__device__ float  g_cs[Bq * NCHUNK * Kk];
__device__ int    g_ci[Bq * NCHUNK * Kk];
__device__ float  g_w[Bq * Kk];
__device__ int    g_tok[Bq * Kk];
__device__ float  g_sumw[Bq];
__device__ float  g_pm[Bq * 4];
__device__ float  g_ps[Bq * 4];
__device__ __half g_qh[Bq * Dd];           // fp16 Q

// ---------------- helpers ----------------
__device__ __forceinline__ unsigned smem_u32(const void* p) {
    unsigned a;
    asm("{ .reg .u64 t; cvta.to.shared.u64 t, %1; cvt.u32.u64 %0, t; }" : "=r"(a) : "l"(p));
    return a;
}
__device__ __forceinline__ void cp16(unsigned dst, const void* src) {
    asm volatile("cp.async.cg.shared.global [%0], [%1], 16;" :: "r"(dst), "l"(src));
}
__device__ __forceinline__ void cp_commit() { asm volatile("cp.async.commit_group;" ::: "memory"); }
template<int N> __device__ __forceinline__ void cp_wait() { asm volatile("cp.async.wait_group %0;" :: "n"(N) : "memory"); }

__device__ __forceinline__ unsigned cvt_h2(float lo, float hi) {
    unsigned r;
    asm("cvt.rn.f16x2.f32 %0, %1, %2;" : "=r"(r) : "f"(hi), "f"(lo));
    return r;
}
__device__ __forceinline__ void ldm4(unsigned r[4], unsigned addr) {
    asm volatile("ldmatrix.sync.aligned.m8n8.x4.shared.b16 {%0,%1,%2,%3}, [%4];"
                 : "=r"(r[0]), "=r"(r[1]), "=r"(r[2]), "=r"(r[3]) : "r"(addr));
}
__device__ __forceinline__ float4 lds128(unsigned addr) {
    float4 v;
    asm volatile("ld.shared.v4.f32 {%0,%1,%2,%3}, [%4];"
                 : "=f"(v.x), "=f"(v.y), "=f"(v.z), "=f"(v.w) : "r"(addr));
    return v;
}
__device__ __forceinline__ void sts64(unsigned addr, unsigned w0, unsigned w1) {
    asm volatile("st.shared.v2.b32 [%0], {%1,%2};" :: "r"(addr), "r"(w0), "r"(w1));
}
__device__ __forceinline__ void mma_f16(float c[4],
                                        unsigned a0, unsigned a1, unsigned a2, unsigned a3,
                                        unsigned b0, unsigned b1) {
    asm volatile(
        "mma.sync.aligned.m16n8k16.row.col.f32.f16.f16.f32 "
        "{%0,%1,%2,%3}, {%4,%5,%6,%7}, {%8,%9}, {%0,%1,%2,%3};"
        : "+f"(c[0]), "+f"(c[1]), "+f"(c[2]), "+f"(c[3])
        : "r"(a0), "r"(a1), "r"(a2), "r"(a3), "r"(b0), "r"(b1));
}

// =====================================================================
// Kernel 0 (fused): blocks [0,256) = per-(row,quarter) softmax stats;
//                   blocks [256,280) = Q fp32 -> fp16
// =====================================================================
__global__ __launch_bounds__(256)
void k_pre(const float* __restrict__ qh, const float* __restrict__ bl) {
    if (blockIdx.x >= 256) {
        int i = (blockIdx.x - 256) * 256 + threadIdx.x;
        #pragma unroll
        for (int s = 0; s < 8; ++s) {
            g_qh[i] = __float2half_rn(qh[i]);
            i += 24 * 256;
        }
        return;
    }
    __shared__ float red[8];
    __shared__ float s_bc;
    const int b = blockIdx.x >> 2, p = blockIdx.x & 3;
    const int tid = threadIdx.x;
    const int wid = tid >> 5, lid = tid & 31;
    const size_t rowoff = (size_t)b * Vv;
    const float* row = bl + rowoff;
    const int vs = (p * Vv) / 4, ve = ((p + 1) * Vv) / 4;
    const int a0 = vs + (int)((4u - (unsigned)((rowoff + vs) & 3u)) & 3u);
    const int n4 = (ve - a0) >> 2;
    const float4* rowa = (const float4*)(row + a0);

    float m = -3.4e38f;
    for (int i = tid; i < n4; i += 256) {
        float4 v = rowa[i];
        m = fmaxf(m, fmaxf(fmaxf(v.x, v.y), fmaxf(v.z, v.w)));
    }
    if (vs + tid < a0) m = fmaxf(m, row[vs + tid]);
    for (int v = a0 + 4 * n4 + tid; v < ve; v += 256) m = fmaxf(m, row[v]);
    #pragma unroll
    for (int off = 16; off > 0; off >>= 1) m = fmaxf(m, __shfl_xor_sync(0xffffffffu, m, off));
    if (lid == 0) red[wid] = m;
    __syncthreads();
    if (tid < 8) {
        float x = red[tid];
        #pragma unroll
        for (int off = 4; off > 0; off >>= 1) x = fmaxf(x, __shfl_xor_sync(0xffu, x, off));
        if (tid == 0) { s_bc = x; g_pm[b * 4 + p] = x; }
    }
    __syncthreads();
    const float rm = s_bc;

    float s = 0.f;
    for (int i = tid; i < n4; i += 256) {
        float4 v = rowa[i];
        s += __expf(v.x - rm) + __expf(v.y - rm) + __expf(v.z - rm) + __expf(v.w - rm);
    }
    if (vs + tid < a0) s += __expf(row[vs + tid] - rm);
    for (int v = a0 + 4 * n4 + tid; v < ve; v += 256) s += __expf(row[v] - rm);
    #pragma unroll
    for (int off = 16; off > 0; off >>= 1) s += __shfl_xor_sync(0xffffffffu, s, off);
    if (lid == 0) red[wid] = s;
    __syncthreads();
    if (tid < 8) {
        float x = red[tid];
        #pragma unroll
        for (int off = 4; off > 0; off >>= 1) x += __shfl_xor_sync(0xffu, x, off);
        if (tid == 0) g_ps[b * 4 + p] = x;
    }
}

// =====================================================================
// Kernel 1: fp16 MMA; 3-stage fp32 K ring, fp16 packed IN PLACE,
// cp.async for kc+2 issued at TOP of iteration. (rd13 proven verbatim)
// =====================================================================
__device__ __forceinline__ void issue_stage(unsigned smb, int tid,
                                            const float* __restrict__ keys,
                                            int kBase, int kc) {
    const int r0 = tid >> 3, jw = tid & 7;
    const unsigned kdst0 = smb + (kc % 3) * K32STG + jw * 16;
    const float* ksrc0 = keys + (size_t)(kBase + r0) * Dd + kc * 32 + jw * 4;
    #pragma unroll
    for (int p = 0; p < 8; ++p)
        cp16(kdst0 + (r0 + 32 * p) * K32P, ksrc0 + (size_t)(32 * p) * Dd);
    const int qr = tid >> 2, qc = tid & 3;
    cp16(smb + SMO_Q + (kc % 3) * QSTG + qr * QPITCH + qc * 16,
         g_qh + qr * Dd + kc * 32 + qc * 8);
}

__global__ void __launch_bounds__(256, 2)
k_scores_f16(const float* __restrict__ keys) {
    extern __shared__ char sm[];
    const unsigned smb = smem_u32(sm);
    float* k2s = (float*)(sm + SMO_K2);
    float* sT  = (float*)sm;                     // 64 x 264 f32, post-mainloop

    const int tid = threadIdx.x;
    const int w = tid >> 5, lane = tid & 31;
    const int g = lane >> 2, t = lane & 3;
    const int kBase = blockIdx.x * KPC;

    const int r0 = tid >> 3, jw = tid & 7;
    const unsigned packRd = r0 * K32P + jw * 16;
    const unsigned packWr = r0 * K32P + (r0 & 3) * 16 + jw * 8;

    const unsigned aRow = (lane & 7) + ((lane >> 3) & 1) * 8;
    const unsigned aCol = (lane >> 4) * 16;
    unsigned aOff[2];
    #pragma unroll
    for (int m = 0; m < 2; ++m) {
        const unsigned row = w * 32 + m * 16 + aRow;
        aOff[m] = row * K32P + (row & 3) * 16 + aCol;
    }
    const unsigned bRow = lane & 7;
    const unsigned bNt  = (lane >> 4) & 1;
    const unsigned bKo  = ((lane >> 3) & 1) * 16;
    const unsigned bOff = (bNt * 8 + bRow) * QPITCH + bKo;

    float c[2][8][4];
    #pragma unroll
    for (int m = 0; m < 2; ++m)
        #pragma unroll
        for (int n = 0; n < 8; ++n)
            #pragma unroll
            for (int v = 0; v < 4; ++v) c[m][n][v] = 0.f;
    float k2a[8];
    #pragma unroll
    for (int p = 0; p < 8; ++p) k2a[p] = 0.f;

    issue_stage(smb, tid, keys, kBase, 0); cp_commit();
    issue_stage(smb, tid, keys, kBase, 1); cp_commit();

    for (int kc = 0; kc < NKC; ++kc) {
        cp_wait<1>();
        __syncthreads();

        if (kc + 2 < NKC) issue_stage(smb, tid, keys, kBase, kc + 2);
        cp_commit();

        // pack(kc) IN PLACE (rd13-proven): 2 groups of 4 row-sets
        {
            const unsigned stg = smb + (kc % 3) * K32STG;
            #pragma unroll
            for (int h = 0; h < 2; ++h) {
                float4 x[4];
                #pragma unroll
                for (int q4 = 0; q4 < 4; ++q4)
                    x[q4] = lds128(stg + packRd + (h * 4 + q4) * 32 * K32P);
                __syncwarp();
                #pragma unroll
                for (int q4 = 0; q4 < 4; ++q4) {
                    const int p = h * 4 + q4;
                    float4 v = x[q4];
                    k2a[p] = fmaf(v.x, v.x, k2a[p]); k2a[p] = fmaf(v.y, v.y, k2a[p]);
                    k2a[p] = fmaf(v.z, v.z, k2a[p]); k2a[p] = fmaf(v.w, v.w, k2a[p]);
                    sts64(stg + packWr + p * 32 * K32P, cvt_h2(v.x, v.y), cvt_h2(v.z, v.w));
                }
            }
        }
        __syncthreads();

        // MMA(kc)
        {
            const unsigned kst = smb + (kc % 3) * K32STG;
            const unsigned qst = smb + SMO_Q + (kc % 3) * QSTG + bOff;
            #pragma unroll
            for (int ks = 0; ks < 2; ++ks) {
                unsigned A0[4], A1[4];
                ldm4(A0, kst + aOff[0] + ks * 32);
                ldm4(A1, kst + aOff[1] + ks * 32);
                #pragma unroll
                for (int np = 0; np < 4; ++np) {
                    unsigned B[4];
                    ldm4(B, qst + np * (16 * QPITCH) + ks * 32);
                    mma_f16(c[0][2 * np],     A0[0], A0[1], A0[2], A0[3], B[0], B[1]);
                    mma_f16(c[0][2 * np + 1], A0[0], A0[1], A0[2], A0[3], B[2], B[3]);
                    mma_f16(c[1][2 * np],     A1[0], A1[1], A1[2], A1[3], B[0], B[1]);
                    mma_f16(c[1][2 * np + 1], A1[0], A1[1], A1[2], A1[3], B[2], B[3]);
                }
            }
        }
    }
    cp_wait<0>();
    __syncthreads();

    #pragma unroll
    for (int p = 0; p < 8; ++p) {
        float s = k2a[p];
        #pragma unroll
        for (int off = 1; off < 8; off <<= 1) s += __shfl_xor_sync(0xffffffffu, s, off);
        if (jw == 0) k2s[r0 + 32 * p] = 0.5f * s;
    }
    __syncthreads();

    #pragma unroll
    for (int m = 0; m < 2; ++m) {
        const int k0 = w * 32 + m * 16 + g;
        const float h0 = k2s[k0], h1 = k2s[k0 + 8];
        #pragma unroll
        for (int n = 0; n < 8; ++n) {
            const int q0 = n * 8 + 2 * t;
            sT[q0 * 264 + k0]           = c[m][n][0] - h0;
            sT[(q0 + 1) * 264 + k0]     = c[m][n][1] - h0;
            sT[q0 * 264 + k0 + 8]       = c[m][n][2] - h1;
            sT[(q0 + 1) * 264 + k0 + 8] = c[m][n][3] - h1;
        }
    }
    __syncthreads();

    {
        const int q = tid >> 2, part = tid & 3;
        float lv[8]; int li[8];
        #pragma unroll
        for (int j = 0; j < 8; ++j) { lv[j] = -3.4e38f; li[j] = 0; }
        const float* row = sT + q * 264 + part * 64;
        #pragma unroll 4
        for (int i = 0; i < 16; ++i) {
            float4 vv = *reinterpret_cast<const float4*>(row + i * 4);
            int bidx = kBase + part * 64 + i * 4;
            float vs[4] = {vv.x, vv.y, vv.z, vv.w};
            #pragma unroll
            for (int cc = 0; cc < 4; ++cc) {
                if (vs[cc] > lv[7]) {
                    lv[7] = vs[cc]; li[7] = bidx + cc;
                    #pragma unroll
                    for (int tt = 7; tt >= 1; --tt)
                        if (lv[tt] > lv[tt - 1]) {
                            float tv = lv[tt]; lv[tt] = lv[tt - 1]; lv[tt - 1] = tv;
                            int   ti = li[tt]; li[tt] = li[tt - 1]; li[tt - 1] = ti;
                        }
                }
            }
        }
        const int sl = lane & 3;
        for (int r = 0; r < Kk; ++r) {
            float mv = lv[0]; int mi = li[0]; int ml = sl;
            #pragma unroll
            for (int off = 1; off < 4; off <<= 1) {
                float ov = __shfl_xor_sync(0xffffffffu, mv, off);
                int   oi = __shfl_xor_sync(0xffffffffu, mi, off);
                int   ol = __shfl_xor_sync(0xffffffffu, ml, off);
                if (ov > mv || (ov == mv && ol < ml)) { mv = ov; mi = oi; ml = ol; }
            }
            if (ml == sl) {
                #pragma unroll
                for (int tt = 0; tt < 7; ++tt) { lv[tt] = lv[tt + 1]; li[tt] = li[tt + 1]; }
                lv[7] = -3.4e38f;
            }
            if (sl == 0) {
                size_t o = ((size_t)q * NCHUNK + blockIdx.x) * Kk + r;
                g_cs[o] = mv; g_ci[o] = mi;
            }
        }
    }
}

// =====================================================================
// Kernel 2: register-sorted pop-max top-16 -> exact fp32 rescore -> top-8
// =====================================================================
__global__ __launch_bounds__(256)
void k_topk(const float* __restrict__ qh, const float* __restrict__ keys,
            const void* __restrict__ values_raw) {
    __shared__ float sv[16 * 256];
    __shared__ int   si[16 * 256];
    __shared__ float wval[8];
    __shared__ int   wtid[8];
    __shared__ int   s_win;
    __shared__ int   topi[TOPC];
    __shared__ float exacts[TOPC];
    __shared__ int   is64;

    const int b = blockIdx.x, tid = threadIdx.x;
    const int wid = tid >> 5, lid = tid & 31;

    if (tid == 0) is64 = 1;
    __syncthreads();
    {
        const int2* vv = (const int2*)values_raw;
        int bad = 0;
        #pragma unroll
        for (int s = 0; s < 16; ++s) bad |= vv[tid + s * 256].y;
        if (bad != 0) is64 = 0;
    }

    float lv[16]; int li[16];
    #pragma unroll
    for (int j = 0; j < 16; ++j) { lv[j] = -3.4e38f; li[j] = 0; }
    const size_t base = (size_t)b * (NCHUNK * Kk);
    for (int s = 0; s < 32; ++s) {
        int j = tid + s * 256;
        float v = g_cs[base + j];
        int  ix = g_ci[base + j];
        if (v > lv[15]) {
            lv[15] = v; li[15] = ix;
            #pragma unroll
            for (int tt = 15; tt >= 1; --tt)
                if (lv[tt] > lv[tt - 1]) {
                    float tv = lv[tt]; lv[tt] = lv[tt - 1]; lv[tt - 1] = tv;
                    int   ti = li[tt]; li[tt] = li[tt - 1]; li[tt - 1] = ti;
                }
        }
    }
    #pragma unroll
    for (int j = 0; j < 16; ++j) { sv[j * 256 + tid] = lv[j]; si[j * 256 + tid] = li[j]; }

    int   cur = 0;
    float curval = lv[0];
    for (int r = 0; r < TOPC; ++r) {
        float v = curval; int who = tid;
        #pragma unroll
        for (int off = 16; off > 0; off >>= 1) {
            float ov = __shfl_xor_sync(0xffffffffu, v, off);
            int   ow = __shfl_xor_sync(0xffffffffu, who, off);
            if (ov > v || (ov == v && ow < who)) { v = ov; who = ow; }
        }
        if (lid == 0) { wval[wid] = v; wtid[wid] = who; }
        __syncthreads();
        if (tid == 0) {
            float bv = wval[0]; int bw = wtid[0];
            #pragma unroll
            for (int i = 1; i < 8; ++i)
                if (wval[i] > bv || (wval[i] == bv && wtid[i] < bw)) { bv = wval[i]; bw = wtid[i]; }
            s_win = bw;
        }
        __syncthreads();
        if (tid == s_win) {
            topi[r] = si[cur * 256 + tid];
            ++cur;
            curval = (cur < 16) ? sv[cur * 256 + tid] : -3.4e38f;
        }
        __syncthreads();
    }

    {
        int j = tid >> 4, l = tid & 15;
        const float* kr = keys + (size_t)topi[j] * Dd;
        const float* qr = qh + (size_t)b * Dd;
        float dot = 0.f, kk = 0.f;
        for (int d = l; d < Dd; d += 16) {
            float kv = kr[d];
            dot = fmaf(qr[d], kv, dot);
            kk  = fmaf(kv, kv, kk);
        }
        #pragma unroll
        for (int off = 8; off > 0; off >>= 1) {
            dot += __shfl_xor_sync(0xffffffffu, dot, off);
            kk  += __shfl_xor_sync(0xffffffffu, kk, off);
        }
        if (l == 0) exacts[j] = dot - 0.5f * kk;
    }
    __syncthreads();

    if (tid == 0) {
        int order[Kk]; unsigned used = 0;
        for (int r = 0; r < Kk; ++r) {
            float best = -3.4e38f; int bj = 0;
            for (int j = 0; j < TOPC; ++j)
                if (!((used >> j) & 1u) && exacts[j] > best) { best = exacts[j]; bj = j; }
            used |= 1u << bj; order[r] = bj;
        }
        float m = exacts[order[0]];
        float e[Kk], se = 0.f;
        for (int r = 0; r < Kk; ++r) { e[r] = expf(2.f * (exacts[order[r]] - m) / TEMP); se += e[r]; }
        float sw = 0.f;
        for (int r = 0; r < Kk; ++r) {
            float wv = e[r] / se;
            g_w[b * Kk + r] = wv; sw += wv;
            int gi = topi[order[r]];
            int tok = is64 ? (int)((const long long*)values_raw)[gi]
                           : ((const int*)values_raw)[gi];
            g_tok[b * Kk + r] = tok;
        }
        g_sumw[b] = sw;
    }
}

// =====================================================================
// Kernel 3: final mix; alignment-peeled float4, fast-math exp/log
// =====================================================================
__global__ __launch_bounds__(256)
void k_final(const float* __restrict__ bl, float* __restrict__ out, long long out_size) {
    __shared__ float ws[Kk]; __shared__ int ts[Kk];
    __shared__ float s_rm, s_rs, s_sw;
    const int b = blockIdx.y, tid = threadIdx.x;
    if (tid < Kk) { ws[tid] = g_w[b * Kk + tid]; ts[tid] = g_tok[b * Kk + tid]; }
    if (tid == 8)  s_sw = g_sumw[b];
    if (tid == 0) {
        float m0 = fmaxf(fmaxf(g_pm[b * 4], g_pm[b * 4 + 1]),
                         fmaxf(g_pm[b * 4 + 2], g_pm[b * 4 + 3]));
        float ss = 0.f;
        #pragma unroll
        for (int i = 0; i < 4; ++i) ss += g_ps[b * 4 + i] * expf(g_pm[b * 4 + i] - m0);
        s_rm = m0; s_rs = ss;
    }
    __syncthreads();

    const float rm = s_rm, rs = s_rs;
    const float Z = s_sw + (float)Vv * EPSV;
    const size_t BV = (size_t)Bq * Vv;
    const size_t rowoff = (size_t)b * Vv;
    const int mis = (int)((4u - ((unsigned)(rowoff & 3u))) & 3u);

    auto emit = [&](int v) {
        const size_t o = rowoff + v;
        float blv = bl[o];
        float tp = 0.f;
        #pragma unroll
        for (int j = 0; j < Kk; ++j) if (ts[j] == v) tp += ws[j];
        float pk = (tp + EPSV) / Z;
        float pb = __expf(blv - rm) / rs;
        float pi = (1.0f - LAM) * pb + LAM * pk;
        if ((long long)o < out_size)            out[o]          = __logf(pi);
        if ((long long)(BV + o) < out_size)     out[BV + o]     = blv;
        if ((long long)(2 * BV + o) < out_size) out[2 * BV + o] = __logf(tp + EPSV);
    };

    const int v4 = mis + (blockIdx.x * 256 + tid) * 4;
    if (v4 + 4 <= Vv) {
        const size_t off = rowoff + v4;
        if ((long long)(2 * BV + off + 4) <= out_size) {
            float4 blv = *(const float4*)(bl + off);
            float tp[4] = {0.f, 0.f, 0.f, 0.f};
            #pragma unroll
            for (int j = 0; j < Kk; ++j) {
                int d = ts[j] - v4;
                if ((unsigned)d < 4u) tp[d] += ws[j];
            }
            float bv[4] = {blv.x, blv.y, blv.z, blv.w};
            float4 o1, o3;
            float* o1p = &o1.x; float* o3p = &o3.x;
            #pragma unroll
            for (int cidx = 0; cidx < 4; ++cidx) {
                float pk = (tp[cidx] + EPSV) / Z;
                float pb = __expf(bv[cidx] - rm) / rs;
                o1p[cidx] = __logf((1.0f - LAM) * pb + LAM * pk);
                o3p[cidx] = __logf(tp[cidx] + EPSV);
            }
            *(float4*)(out + off)          = o1;
            *(float4*)(out + BV + off)     = blv;
            *(float4*)(out + 2 * BV + off) = o3;
        } else {
            #pragma unroll
            for (int cidx = 0; cidx < 4; ++cidx) emit(v4 + cidx);
        }
    } else {
        for (int v = v4; v < Vv; ++v) emit(v);
    }
    if (blockIdx.x == 0 && tid < mis) emit(tid);
}

// =====================================================================
extern "C" void kernel_launch(void* const* d_in, const int* in_sizes, int n_in,
                              void* d_out, int out_size) {
    const float* qh   = (const float*)d_in[0];   // [B, D] f32
    const float* bl   = (const float*)d_in[1];   // [B, V] f32
    const float* keys = (const float*)d_in[2];   // [N, D] f32
    const void*  vals = d_in[3];                 // [N] int64 (or int32)
    float* out = (float*)d_out;

    cudaFuncSetAttribute(k_scores_f16, cudaFuncAttributeMaxDynamicSharedMemorySize, SMEM_BYTES);

    k_pre<<<280, 256>>>(qh, bl);
    k_scores_f16<<<NCHUNK, 256, SMEM_BYTES>>>(keys);
    k_topk<<<Bq, 256>>>(qh, keys, vals);
    dim3 g3((Vv / 4 + 256) / 256, Bq);
    k_final<<<g3, 256>>>(bl, out, (long long)out_size);
}

// round 17
// speedup vs baseline: 1.2575x; 1.0159x over previous
#include <cuda_runtime.h>
#include <cuda_fp16.h>
#include <math.h>
#include <stdint.h>

// ---------------- problem constants ----------------
#define Bq   64
#define Dd   768
#define Nn   262144
#define Vv   50257
#define Kk   8
#define TEMP 10.0f
#define LAM  0.25f
#define EPSV 1e-10f

#define KPC    256                 // keys per CTA
#define NCHUNK (Nn / KPC)          // 1024
#define NKC    24                  // 768/32 d-tiles
#define TOPC   16                  // candidates rescored exactly

// smem layout (bytes)
#define K32P   128                 // K row pitch (fp32 tile; fp16 packed in place)
#define K32STG (KPC * K32P)        // 32768 per stage, 3 stages @ 0
#define QPITCH 80
#define QSTG   (64 * QPITCH)       // 5120 per Q slot (3 slots)
#define SMO_Q    (3 * K32STG)      // 98304
#define SMO_K2   (SMO_Q + 3 * QSTG)  // 113664
#define SMEM_BYTES (SMO_K2 + 1024)   // 114688  -> 2 CTAs/SM

// ---------------- scratch ----------------
__device__ float  g_cs[Bq * NCHUNK * Kk];
__device__ int    g_ci[Bq * NCHUNK * Kk];
__device__ float  g_w[Bq * Kk];
__device__ int    g_tok[Bq * Kk];
__device__ float  g_sumw[Bq];
__device__ float  g_pm[Bq * 4];
__device__ float  g_ps[Bq * 4];
__device__ __half g_qh[Bq * Dd];           // fp16 Q

// ---------------- helpers ----------------
__device__ __forceinline__ unsigned smem_u32(const void* p) {
    unsigned a;
    asm("{ .reg .u64 t; cvta.to.shared.u64 t, %1; cvt.u32.u64 %0, t; }" : "=r"(a) : "l"(p));
    return a;
}
__device__ __forceinline__ void cp16(unsigned dst, const void* src) {
    asm volatile("cp.async.cg.shared.global [%0], [%1], 16;" :: "r"(dst), "l"(src));
}
__device__ __forceinline__ void cp_commit() { asm volatile("cp.async.commit_group;" ::: "memory"); }
template<int N> __device__ __forceinline__ void cp_wait() { asm volatile("cp.async.wait_group %0;" :: "n"(N) : "memory"); }

__device__ __forceinline__ unsigned cvt_h2(float lo, float hi) {
    unsigned r;
    asm("cvt.rn.f16x2.f32 %0, %1, %2;" : "=r"(r) : "f"(hi), "f"(lo));
    return r;
}
__device__ __forceinline__ void ldm4(unsigned r[4], unsigned addr) {
    asm volatile("ldmatrix.sync.aligned.m8n8.x4.shared.b16 {%0,%1,%2,%3}, [%4];"
                 : "=r"(r[0]), "=r"(r[1]), "=r"(r[2]), "=r"(r[3]) : "r"(addr));
}
__device__ __forceinline__ float4 lds128(unsigned addr) {
    float4 v;
    asm volatile("ld.shared.v4.f32 {%0,%1,%2,%3}, [%4];"
                 : "=f"(v.x), "=f"(v.y), "=f"(v.z), "=f"(v.w) : "r"(addr));
    return v;
}
__device__ __forceinline__ void sts64(unsigned addr, unsigned w0, unsigned w1) {
    asm volatile("st.shared.v2.b32 [%0], {%1,%2};" :: "r"(addr), "r"(w0), "r"(w1));
}
__device__ __forceinline__ void mma_f16(float c[4],
                                        unsigned a0, unsigned a1, unsigned a2, unsigned a3,
                                        unsigned b0, unsigned b1) {
    asm volatile(
        "mma.sync.aligned.m16n8k16.row.col.f32.f16.f16.f32 "
        "{%0,%1,%2,%3}, {%4,%5,%6,%7}, {%8,%9}, {%0,%1,%2,%3};"
        : "+f"(c[0]), "+f"(c[1]), "+f"(c[2]), "+f"(c[3])
        : "r"(a0), "r"(a1), "r"(a2), "r"(a3), "r"(b0), "r"(b1));
}

// online softmax merge: (m,s) <- (m,s) + (om,os)
__device__ __forceinline__ void sm_merge(float& m, float& s, float om, float os) {
    float M = fmaxf(m, om);
    s = s * __expf(m - M) + os * __expf(om - M);
    m = M;
}

// =====================================================================
// Kernel 0 (fused): blocks [0,256) = per-(row,quarter) ONLINE softmax
//                   stats (single pass); blocks [256,280) = Q fp32->fp16
// =====================================================================
__global__ __launch_bounds__(256)
void k_pre(const float* __restrict__ qh, const float* __restrict__ bl) {
    if (blockIdx.x >= 256) {
        int i = (blockIdx.x - 256) * 256 + threadIdx.x;
        #pragma unroll
        for (int s = 0; s < 8; ++s) {
            g_qh[i] = __float2half_rn(qh[i]);
            i += 24 * 256;
        }
        return;
    }
    __shared__ float redm[8], reds[8];
    const int b = blockIdx.x >> 2, p = blockIdx.x & 3;
    const int tid = threadIdx.x;
    const int wid = tid >> 5, lid = tid & 31;
    const size_t rowoff = (size_t)b * Vv;
    const float* row = bl + rowoff;
    const int vs = (p * Vv) / 4, ve = ((p + 1) * Vv) / 4;
    const int a0 = vs + (int)((4u - (unsigned)((rowoff + vs) & 3u)) & 3u);
    const int n4 = (ve - a0) >> 2;
    const float4* rowa = (const float4*)(row + a0);

    float m = -3.4e38f, s = 0.f;
    for (int i = tid; i < n4; i += 256) {
        float4 v = rowa[i];
        float m4 = fmaxf(fmaxf(v.x, v.y), fmaxf(v.z, v.w));
        float s4 = __expf(v.x - m4) + __expf(v.y - m4) + __expf(v.z - m4) + __expf(v.w - m4);
        sm_merge(m, s, m4, s4);
    }
    if (vs + tid < a0) sm_merge(m, s, row[vs + tid], 1.f);
    for (int v = a0 + 4 * n4 + tid; v < ve; v += 256) sm_merge(m, s, row[v], 1.f);
    #pragma unroll
    for (int off = 16; off > 0; off >>= 1) {
        float om = __shfl_xor_sync(0xffffffffu, m, off);
        float os = __shfl_xor_sync(0xffffffffu, s, off);
        sm_merge(m, s, om, os);
    }
    if (lid == 0) { redm[wid] = m; reds[wid] = s; }
    __syncthreads();
    if (tid < 8) {
        float mm = redm[tid], ss = reds[tid];
        #pragma unroll
        for (int off = 4; off > 0; off >>= 1) {
            float om = __shfl_xor_sync(0xffu, mm, off);
            float os = __shfl_xor_sync(0xffu, ss, off);
            sm_merge(mm, ss, om, os);
        }
        if (tid == 0) { g_pm[b * 4 + p] = mm; g_ps[b * 4 + p] = ss; }
    }
}

// =====================================================================
// Kernel 1: fp16 MMA; 3-stage fp32 K ring, fp16 packed IN PLACE,
// SINGLE barrier per kc: wait -> pack(own bytes) -> BAR -> issue -> MMA
// =====================================================================
__device__ __forceinline__ void issue_stage(unsigned smb, int tid,
                                            const float* __restrict__ keys,
                                            int kBase, int kc) {
    const int r0 = tid >> 3, jw = tid & 7;
    const unsigned kdst0 = smb + (kc % 3) * K32STG + jw * 16;
    const float* ksrc0 = keys + (size_t)(kBase + r0) * Dd + kc * 32 + jw * 4;
    #pragma unroll
    for (int p = 0; p < 8; ++p)
        cp16(kdst0 + (r0 + 32 * p) * K32P, ksrc0 + (size_t)(32 * p) * Dd);
    const int qr = tid >> 2, qc = tid & 3;
    cp16(smb + SMO_Q + (kc % 3) * QSTG + qr * QPITCH + qc * 16,
         g_qh + qr * Dd + kc * 32 + qc * 8);
}

__global__ void __launch_bounds__(256, 2)
k_scores_f16(const float* __restrict__ keys) {
    extern __shared__ char sm[];
    const unsigned smb = smem_u32(sm);
    float* k2s = (float*)(sm + SMO_K2);
    float* sT  = (float*)sm;                     // 64 x 264 f32, post-mainloop

    const int tid = threadIdx.x;
    const int w = tid >> 5, lane = tid & 31;
    const int g = lane >> 2, t = lane & 3;
    const int kBase = blockIdx.x * KPC;

    const int r0 = tid >> 3, jw = tid & 7;
    const unsigned packRd = r0 * K32P + jw * 16;
    const unsigned packWr = r0 * K32P + (r0 & 3) * 16 + jw * 8;

    const unsigned aRow = (lane & 7) + ((lane >> 3) & 1) * 8;
    const unsigned aCol = (lane >> 4) * 16;
    unsigned aOff[2];
    #pragma unroll
    for (int m = 0; m < 2; ++m) {
        const unsigned row = w * 32 + m * 16 + aRow;
        aOff[m] = row * K32P + (row & 3) * 16 + aCol;
    }
    const unsigned bRow = lane & 7;
    const unsigned bNt  = (lane >> 4) & 1;
    const unsigned bKo  = ((lane >> 3) & 1) * 16;
    const unsigned bOff = (bNt * 8 + bRow) * QPITCH + bKo;

    float c[2][8][4];
    #pragma unroll
    for (int m = 0; m < 2; ++m)
        #pragma unroll
        for (int n = 0; n < 8; ++n)
            #pragma unroll
            for (int v = 0; v < 4; ++v) c[m][n][v] = 0.f;
    float k2a[8];
    #pragma unroll
    for (int p = 0; p < 8; ++p) k2a[p] = 0.f;

    issue_stage(smb, tid, keys, kBase, 0); cp_commit();
    issue_stage(smb, tid, keys, kBase, 1); cp_commit();

    for (int kc = 0; kc < NKC; ++kc) {
        cp_wait<1>();                            // this thread's stage-kc bytes landed

        // pack(kc) IN PLACE — reads exactly this thread's copied bytes
        {
            const unsigned stg = smb + (kc % 3) * K32STG;
            #pragma unroll
            for (int h = 0; h < 2; ++h) {
                float4 x[4];
                #pragma unroll
                for (int q4 = 0; q4 < 4; ++q4)
                    x[q4] = lds128(stg + packRd + (h * 4 + q4) * 32 * K32P);
                __syncwarp();
                #pragma unroll
                for (int q4 = 0; q4 < 4; ++q4) {
                    const int p = h * 4 + q4;
                    float4 v = x[q4];
                    k2a[p] = fmaf(v.x, v.x, k2a[p]); k2a[p] = fmaf(v.y, v.y, k2a[p]);
                    k2a[p] = fmaf(v.z, v.z, k2a[p]); k2a[p] = fmaf(v.w, v.w, k2a[p]);
                    sts64(stg + packWr + p * 32 * K32P, cvt_h2(v.x, v.y), cvt_h2(v.z, v.w));
                }
            }
        }
        __syncthreads();   // all packs + all Q(kc) copies visible; MMA(kc-1) done everywhere

        // early prefetch kc+2 (stage (kc+2)%3 had last reader MMA(kc-1), done)
        if (kc + 2 < NKC) issue_stage(smb, tid, keys, kBase, kc + 2);
        cp_commit();

        // MMA(kc)
        {
            const unsigned kst = smb + (kc % 3) * K32STG;
            const unsigned qst = smb + SMO_Q + (kc % 3) * QSTG + bOff;
            #pragma unroll
            for (int ks = 0; ks < 2; ++ks) {
                unsigned A0[4], A1[4];
                ldm4(A0, kst + aOff[0] + ks * 32);
                ldm4(A1, kst + aOff[1] + ks * 32);
                #pragma unroll
                for (int np = 0; np < 4; ++np) {
                    unsigned B[4];
                    ldm4(B, qst + np * (16 * QPITCH) + ks * 32);
                    mma_f16(c[0][2 * np],     A0[0], A0[1], A0[2], A0[3], B[0], B[1]);
                    mma_f16(c[0][2 * np + 1], A0[0], A0[1], A0[2], A0[3], B[2], B[3]);
                    mma_f16(c[1][2 * np],     A1[0], A1[1], A1[2], A1[3], B[0], B[1]);
                    mma_f16(c[1][2 * np + 1], A1[0], A1[1], A1[2], A1[3], B[2], B[3]);
                }
            }
        }
    }
    cp_wait<0>();
    __syncthreads();                             // all MMA done; buffers dead

    #pragma unroll
    for (int p = 0; p < 8; ++p) {
        float s = k2a[p];
        #pragma unroll
        for (int off = 1; off < 8; off <<= 1) s += __shfl_xor_sync(0xffffffffu, s, off);
        if (jw == 0) k2s[r0 + 32 * p] = 0.5f * s;
    }
    __syncthreads();

    #pragma unroll
    for (int m = 0; m < 2; ++m) {
        const int k0 = w * 32 + m * 16 + g;
        const float h0 = k2s[k0], h1 = k2s[k0 + 8];
        #pragma unroll
        for (int n = 0; n < 8; ++n) {
            const int q0 = n * 8 + 2 * t;
            sT[q0 * 264 + k0]           = c[m][n][0] - h0;
            sT[(q0 + 1) * 264 + k0]     = c[m][n][1] - h0;
            sT[q0 * 264 + k0 + 8]       = c[m][n][2] - h1;
            sT[(q0 + 1) * 264 + k0 + 8] = c[m][n][3] - h1;
        }
    }
    __syncthreads();

    {
        const int q = tid >> 2, part = tid & 3;
        float lv[8]; int li[8];
        #pragma unroll
        for (int j = 0; j < 8; ++j) { lv[j] = -3.4e38f; li[j] = 0; }
        const float* row = sT + q * 264 + part * 64;
        #pragma unroll 4
        for (int i = 0; i < 16; ++i) {
            float4 vv = *reinterpret_cast<const float4*>(row + i * 4);
            int bidx = kBase + part * 64 + i * 4;
            float vs[4] = {vv.x, vv.y, vv.z, vv.w};
            #pragma unroll
            for (int cc = 0; cc < 4; ++cc) {
                if (vs[cc] > lv[7]) {
                    lv[7] = vs[cc]; li[7] = bidx + cc;
                    #pragma unroll
                    for (int tt = 7; tt >= 1; --tt)
                        if (lv[tt] > lv[tt - 1]) {
                            float tv = lv[tt]; lv[tt] = lv[tt - 1]; lv[tt - 1] = tv;
                            int   ti = li[tt]; li[tt] = li[tt - 1]; li[tt - 1] = ti;
                        }
                }
            }
        }
        const int sl = lane & 3;
        for (int r = 0; r < Kk; ++r) {
            float mv = lv[0]; int mi = li[0]; int ml = sl;
            #pragma unroll
            for (int off = 1; off < 4; off <<= 1) {
                float ov = __shfl_xor_sync(0xffffffffu, mv, off);
                int   oi = __shfl_xor_sync(0xffffffffu, mi, off);
                int   ol = __shfl_xor_sync(0xffffffffu, ml, off);
                if (ov > mv || (ov == mv && ol < ml)) { mv = ov; mi = oi; ml = ol; }
            }
            if (ml == sl) {
                #pragma unroll
                for (int tt = 0; tt < 7; ++tt) { lv[tt] = lv[tt + 1]; li[tt] = li[tt + 1]; }
                lv[7] = -3.4e38f;
            }
            if (sl == 0) {
                size_t o = ((size_t)q * NCHUNK + blockIdx.x) * Kk + r;
                g_cs[o] = mv; g_ci[o] = mi;
            }
        }
    }
}

// =====================================================================
// Kernel 2: register-sorted pop-max top-16 -> exact fp32 rescore -> top-8
// =====================================================================
__global__ __launch_bounds__(256)
void k_topk(const float* __restrict__ qh, const float* __restrict__ keys,
            const void* __restrict__ values_raw) {
    __shared__ float sv[16 * 256];
    __shared__ int   si[16 * 256];
    __shared__ float wval[8];
    __shared__ int   wtid[8];
    __shared__ int   s_win;
    __shared__ int   topi[TOPC];
    __shared__ float exacts[TOPC];
    __shared__ int   is64;

    const int b = blockIdx.x, tid = threadIdx.x;
    const int wid = tid >> 5, lid = tid & 31;

    if (tid == 0) is64 = 1;
    __syncthreads();
    {
        const int2* vv = (const int2*)values_raw;
        int bad = 0;
        #pragma unroll
        for (int s = 0; s < 16; ++s) bad |= vv[tid + s * 256].y;
        if (bad != 0) is64 = 0;
    }

    float lv[16]; int li[16];
    #pragma unroll
    for (int j = 0; j < 16; ++j) { lv[j] = -3.4e38f; li[j] = 0; }
    const size_t base = (size_t)b * (NCHUNK * Kk);
    for (int s = 0; s < 32; ++s) {
        int j = tid + s * 256;
        float v = g_cs[base + j];
        int  ix = g_ci[base + j];
        if (v > lv[15]) {
            lv[15] = v; li[15] = ix;
            #pragma unroll
            for (int tt = 15; tt >= 1; --tt)
                if (lv[tt] > lv[tt - 1]) {
                    float tv = lv[tt]; lv[tt] = lv[tt - 1]; lv[tt - 1] = tv;
                    int   ti = li[tt]; li[tt] = li[tt - 1]; li[tt - 1] = ti;
                }
        }
    }
    #pragma unroll
    for (int j = 0; j < 16; ++j) { sv[j * 256 + tid] = lv[j]; si[j * 256 + tid] = li[j]; }

    int   cur = 0;
    float curval = lv[0];
    for (int r = 0; r < TOPC; ++r) {
        float v = curval; int who = tid;
        #pragma unroll
        for (int off = 16; off > 0; off >>= 1) {
            float ov = __shfl_xor_sync(0xffffffffu, v, off);
            int   ow = __shfl_xor_sync(0xffffffffu, who, off);
            if (ov > v || (ov == v && ow < who)) { v = ov; who = ow; }
        }
        if (lid == 0) { wval[wid] = v; wtid[wid] = who; }
        __syncthreads();
        if (tid == 0) {
            float bv = wval[0]; int bw = wtid[0];
            #pragma unroll
            for (int i = 1; i < 8; ++i)
                if (wval[i] > bv || (wval[i] == bv && wtid[i] < bw)) { bv = wval[i]; bw = wtid[i]; }
            s_win = bw;
        }
        __syncthreads();
        if (tid == s_win) {
            topi[r] = si[cur * 256 + tid];
            ++cur;
            curval = (cur < 16) ? sv[cur * 256 + tid] : -3.4e38f;
        }
        __syncthreads();
    }

    {
        int j = tid >> 4, l = tid & 15;
        const float* kr = keys + (size_t)topi[j] * Dd;
        const float* qr = qh + (size_t)b * Dd;
        float dot = 0.f, kk = 0.f;
        for (int d = l; d < Dd; d += 16) {
            float kv = kr[d];
            dot = fmaf(qr[d], kv, dot);
            kk  = fmaf(kv, kv, kk);
        }
        #pragma unroll
        for (int off = 8; off > 0; off >>= 1) {
            dot += __shfl_xor_sync(0xffffffffu, dot, off);
            kk  += __shfl_xor_sync(0xffffffffu, kk, off);
        }
        if (l == 0) exacts[j] = dot - 0.5f * kk;
    }
    __syncthreads();

    if (tid == 0) {
        int order[Kk]; unsigned used = 0;
        for (int r = 0; r < Kk; ++r) {
            float best = -3.4e38f; int bj = 0;
            for (int j = 0; j < TOPC; ++j)
                if (!((used >> j) & 1u) && exacts[j] > best) { best = exacts[j]; bj = j; }
            used |= 1u << bj; order[r] = bj;
        }
        float m = exacts[order[0]];
        float e[Kk], se = 0.f;
        for (int r = 0; r < Kk; ++r) { e[r] = expf(2.f * (exacts[order[r]] - m) / TEMP); se += e[r]; }
        float sw = 0.f;
        for (int r = 0; r < Kk; ++r) {
            float wv = e[r] / se;
            g_w[b * Kk + r] = wv; sw += wv;
            int gi = topi[order[r]];
            int tok = is64 ? (int)((const long long*)values_raw)[gi]
                           : ((const int*)values_raw)[gi];
            g_tok[b * Kk + r] = tok;
        }
        g_sumw[b] = sw;
    }
}

// =====================================================================
// Kernel 3: final mix; 8 elems/thread (2x float4), fast-math exp/log
// =====================================================================
__global__ __launch_bounds__(256)
void k_final(const float* __restrict__ bl, float* __restrict__ out, long long out_size) {
    __shared__ float ws[Kk]; __shared__ int ts[Kk];
    __shared__ float s_rm, s_rs, s_sw;
    const int b = blockIdx.y, tid = threadIdx.x;
    if (tid < Kk) { ws[tid] = g_w[b * Kk + tid]; ts[tid] = g_tok[b * Kk + tid]; }
    if (tid == 8)  s_sw = g_sumw[b];
    if (tid == 0) {
        float m0 = fmaxf(fmaxf(g_pm[b * 4], g_pm[b * 4 + 1]),
                         fmaxf(g_pm[b * 4 + 2], g_pm[b * 4 + 3]));
        float ss = 0.f;
        #pragma unroll
        for (int i = 0; i < 4; ++i) ss += g_ps[b * 4 + i] * expf(g_pm[b * 4 + i] - m0);
        s_rm = m0; s_rs = ss;
    }
    __syncthreads();

    const float rm = s_rm, rs = s_rs;
    const float Z = s_sw + (float)Vv * EPSV;
    const size_t BV = (size_t)Bq * Vv;
    const size_t rowoff = (size_t)b * Vv;
    const int mis = (int)((4u - ((unsigned)(rowoff & 3u))) & 3u);

    auto emit = [&](int v) {
        const size_t o = rowoff + v;
        float blv = bl[o];
        float tp = 0.f;
        #pragma unroll
        for (int j = 0; j < Kk; ++j) if (ts[j] == v) tp += ws[j];
        float pk = (tp + EPSV) / Z;
        float pb = __expf(blv - rm) / rs;
        float pi = (1.0f - LAM) * pb + LAM * pk;
        if ((long long)o < out_size)            out[o]          = __logf(pi);
        if ((long long)(BV + o) < out_size)     out[BV + o]     = blv;
        if ((long long)(2 * BV + o) < out_size) out[2 * BV + o] = __logf(tp + EPSV);
    };

    const int v8 = mis + (blockIdx.x * 256 + tid) * 8;
    if (v8 + 8 <= Vv) {
        const size_t off = rowoff + v8;
        if ((long long)(2 * BV + off + 8) <= out_size) {
            #pragma unroll
            for (int half = 0; half < 2; ++half) {
                const size_t o4 = off + half * 4;
                const int vb = v8 + half * 4;
                float4 blv = *(const float4*)(bl + o4);
                float tp[4] = {0.f, 0.f, 0.f, 0.f};
                #pragma unroll
                for (int j = 0; j < Kk; ++j) {
                    int d = ts[j] - vb;
                    if ((unsigned)d < 4u) tp[d] += ws[j];
                }
                float bv[4] = {blv.x, blv.y, blv.z, blv.w};
                float4 o1, o3;
                float* o1p = &o1.x; float* o3p = &o3.x;
                #pragma unroll
                for (int cidx = 0; cidx < 4; ++cidx) {
                    float pk = (tp[cidx] + EPSV) / Z;
                    float pb = __expf(bv[cidx] - rm) / rs;
                    o1p[cidx] = __logf((1.0f - LAM) * pb + LAM * pk);
                    o3p[cidx] = __logf(tp[cidx] + EPSV);
                }
                *(float4*)(out + o4)          = o1;
                *(float4*)(out + BV + o4)     = blv;
                *(float4*)(out + 2 * BV + o4) = o3;
            }
        } else {
            #pragma unroll
            for (int cidx = 0; cidx < 8; ++cidx) emit(v8 + cidx);
        }
    } else {
        for (int v = v8; v < Vv; ++v) emit(v);
    }
    if (blockIdx.x == 0 && tid < mis) emit(tid);
}

// =====================================================================
extern "C" void kernel_launch(void* const* d_in, const int* in_sizes, int n_in,
                              void* d_out, int out_size) {
    const float* qh   = (const float*)d_in[0];   // [B, D] f32
    const float* bl   = (const float*)d_in[1];   // [B, V] f32
    const float* keys = (const float*)d_in[2];   // [N, D] f32
    const void*  vals = d_in[3];                 // [N] int64 (or int32)
    float* out = (float*)d_out;

    cudaFuncSetAttribute(k_scores_f16, cudaFuncAttributeMaxDynamicSharedMemorySize, SMEM_BYTES);

    k_pre<<<280, 256>>>(qh, bl);
    k_scores_f16<<<NCHUNK, 256, SMEM_BYTES>>>(keys);
    k_topk<<<Bq, 256>>>(qh, keys, vals);
    dim3 g3(25, Bq);
    k_final<<<g3, 256>>>(bl, out, (long long)out_size);
}